// round 10
// baseline (speedup 1.0000x reference)
#include <cuda_runtime.h>
#include <cuda_fp16.h>
#include <math.h>
#include <stdint.h>

#define ROI   116
#define FEAT  6670      // ROI*(ROI-1)/2
#define FEATP 6720      // padded to multiple of 64
#define NB    64        // batch
#define NW    128       // bags per batch
#define BW    8192      // NB*NW
#define DD    1024
#define HH    1024
#define NSTG64 (FEATP / 64)  // 105 K-stages of 64

// ---------------- scratch (device globals; no allocation) ----------------
__device__ __align__(16) __half g_bag[(size_t)BW * FEATP];   // 110 MB
__device__ __align__(16) __half g_w1th[(size_t)DD * FEATP];  // 13.8 MB  [N][K]
__device__ int   g_off[FEAT];
__device__ float g_a[BW];
__device__ float g_bagz0[NB * FEATP];
__device__ float g_bagz[NB * FEATP];
__device__ float g_ccn[2 * FEATP];
__device__ float g_q[NB * HH];
__device__ float g_k2[2 * HH];
__device__ float g_v2[2 * HH];
__device__ float g_fcx[NB * HH];
__device__ float g_t1[NB * DD];

// ---------------- PTX helpers (generic, sm_80-level) ----------------
__device__ __forceinline__ uint32_t smem_u32(const void* p) {
    uint32_t a;
    asm("{ .reg .u64 t; cvta.to.shared.u64 t, %1; cvt.u32.u64 %0, t; }" : "=r"(a) : "l"(p));
    return a;
}
#define CP_ASYNC16(dst, src) \
    asm volatile("cp.async.cg.shared.global [%0], [%1], 16;" \
                 :: "r"(dst), "l"(src) : "memory")
#define CP_COMMIT() asm volatile("cp.async.commit_group;" ::: "memory")
#define CP_WAIT(n)  asm volatile("cp.async.wait_group %0;" :: "n"(n) : "memory")

__device__ __forceinline__ void ldm_x4(uint32_t& r0, uint32_t& r1, uint32_t& r2, uint32_t& r3,
                                       uint32_t addr) {
    asm volatile("ldmatrix.sync.aligned.m8n8.x4.shared.b16 {%0,%1,%2,%3}, [%4];"
                 : "=r"(r0), "=r"(r1), "=r"(r2), "=r"(r3) : "r"(addr));
}
__device__ __forceinline__ void mma16816(float* c, const uint32_t* a, const uint32_t* b) {
    asm volatile(
        "mma.sync.aligned.m16n8k16.row.col.f32.f16.f16.f32 "
        "{%0,%1,%2,%3}, {%4,%5,%6,%7}, {%8,%9}, {%0,%1,%2,%3};"
        : "+f"(c[0]), "+f"(c[1]), "+f"(c[2]), "+f"(c[3])
        : "r"(a[0]), "r"(a[1]), "r"(a[2]), "r"(a[3]), "r"(b[0]), "r"(b[1]));
}
__device__ __forceinline__ float fast_tanh(float x) {
    float e = __expf(2.0f * x);
    return 1.0f - 2.0f / (e + 1.0f);
}

// ---------------- triu index table ----------------
__global__ void init_off_kernel() {
    int i = blockIdx.x;
    int base = i * (ROI - 1) - i * (i - 1) / 2;
    int cnt = ROI - 1 - i;
    for (int jj = threadIdx.x; jj < cnt; jj += blockDim.x)
        g_off[base + jj] = i * ROI + (i + 1 + jj);
}

// ---------------- gather -> fp16 ----------------
__global__ void gather_kernel(const float* __restrict__ FC) {
    int bw = blockIdx.y;
    int f = blockIdx.x * 256 + threadIdx.x;
    if (f < FEATP) {
        float v = 0.f;
        if (f < FEAT) v = FC[(size_t)bw * (ROI * ROI) + g_off[f]];
        g_bag[(size_t)bw * FEATP + f] = __float2half_rn(v);
    }
}

// ---------------- W1 -> W1T fp16 ([N][K], padded); also inits g_a = b2 ----
__global__ void w1t_kernel(const float* __restrict__ W1, const float* __restrict__ b2) {
    __shared__ float t[32][33];
    int kb = blockIdx.x * 32, nb = blockIdx.y * 32;
    int tx = threadIdx.x, ty = threadIdx.y;
    if (blockIdx.x == 0 && blockIdx.y == 0) {
        int tid = ty * 32 + tx;
        float v = b2[0];
        for (int i = tid; i < BW; i += 256) g_a[i] = v;
    }
#pragma unroll
    for (int i = 0; i < 32; i += 8) {
        int k = kb + ty + i;
        t[ty + i][tx] = (k < FEAT) ? W1[(size_t)k * DD + nb + tx] : 0.f;
    }
    __syncthreads();
#pragma unroll
    for (int i = 0; i < 32; i += 8) {
        float v = t[tx][ty + i];
        g_w1th[(size_t)(nb + ty + i) * FEATP + kb + tx] = __float2half_rn(v);
    }
}

// ---------------- HMMA GEMM: S = bag @ W1T^T (fp16), fused tanh/W2 epi ----
// CTA 128x128, 8 warps (4Mx2N), warp tile 32x64. K-stage 64, 3-stage
// pipeline (CP_WAIT(1)), one __syncthreads per stage. rows 144B.
#define LDA       144
#define TILE_B    18432               // 128 rows x 144B
#define STAGE_B   (2 * TILE_B)        // A + B = 36864
#define GEMM_SMEM (3 * STAGE_B)       // 110592

__device__ __forceinline__ void load_stage(uint32_t sdst, int k0, int m0, int n0, int tid) {
    int row = tid >> 1;
    int cb = (tid & 1) * 64;          // byte offset within 128B row half
    uint32_t so = sdst + row * LDA + cb;
    size_t ga = ((size_t)(m0 + row) * FEATP + k0) * 2 + cb;
    size_t gb = ((size_t)(n0 + row) * FEATP + k0) * 2 + cb;
    unsigned long long pa = __cvta_generic_to_global((const char*)g_bag + ga);
    unsigned long long pb = __cvta_generic_to_global((const char*)g_w1th + gb);
    CP_ASYNC16(so,      pa);      CP_ASYNC16(so + 16, pa + 16);
    CP_ASYNC16(so + 32, pa + 32); CP_ASYNC16(so + 48, pa + 48);
    so += TILE_B;
    CP_ASYNC16(so,      pb);      CP_ASYNC16(so + 16, pb + 16);
    CP_ASYNC16(so + 32, pb + 32); CP_ASYNC16(so + 48, pb + 48);
}

__global__ __launch_bounds__(256, 2) void gemm_mma_kernel(const float* __restrict__ b1,
                                                          const float* __restrict__ W2) {
    extern __shared__ char sm[];
    const uint32_t sbase = smem_u32(sm);
    const int tid = threadIdx.x, lane = tid & 31, wid = tid >> 5;
    const int wm = wid & 3, wn = wid >> 2;        // 4 M-warps x 2 N-warps
    const int n0 = blockIdx.x * 128, m0 = blockIdx.y * 128;

    float acc[2][8][4];
#pragma unroll
    for (int mt = 0; mt < 2; mt++)
#pragma unroll
        for (int nt = 0; nt < 8; nt++)
#pragma unroll
            for (int c = 0; c < 4; c++) acc[mt][nt][c] = 0.f;

    load_stage(sbase, 0, m0, n0, tid);             CP_COMMIT();
    load_stage(sbase + STAGE_B, 64, m0, n0, tid);  CP_COMMIT();

    const uint32_t aRowOfs = (uint32_t)(wm * 32 + ((lane >> 3) & 1) * 8 + (lane & 7)) * LDA
                           + (uint32_t)(lane >> 4) * 16;
    const uint32_t bRowOfs = (uint32_t)(wn * 64 + (lane >> 4) * 8 + (lane & 7)) * LDA
                           + (uint32_t)((lane >> 3) & 1) * 16;

    int slot = 0;
    for (int i = 0; i < NSTG64; i++) {
        if (i + 1 < NSTG64) { CP_WAIT(1); } else { CP_WAIT(0); }
        __syncthreads();
        if (i + 2 < NSTG64) {
            int ns = slot + 2; if (ns >= 3) ns -= 3;
            load_stage(sbase + (uint32_t)ns * STAGE_B, (i + 2) * 64, m0, n0, tid);
            CP_COMMIT();
        }
        const uint32_t st = sbase + (uint32_t)slot * STAGE_B;
#pragma unroll
        for (int kk = 0; kk < 4; kk++) {
            uint32_t aH[2][4], bb[8][2];
#pragma unroll
            for (int mt = 0; mt < 2; mt++)
                ldm_x4(aH[mt][0], aH[mt][1], aH[mt][2], aH[mt][3],
                       st + aRowOfs + (uint32_t)mt * 16 * LDA + kk * 32);
#pragma unroll
            for (int p = 0; p < 4; p++)
                ldm_x4(bb[2 * p][0], bb[2 * p][1], bb[2 * p + 1][0], bb[2 * p + 1][1],
                       st + TILE_B + bRowOfs + (uint32_t)p * 16 * LDA + kk * 32);
#pragma unroll
            for (int mt = 0; mt < 2; mt++)
#pragma unroll
                for (int nt = 0; nt < 8; nt++) mma16816(acc[mt][nt], aH[mt], bb[nt]);
        }
        if (++slot == 3) slot = 0;
    }

    // epilogue: per-row sum over n of tanh(S + b1)*W2, reduce, atomicAdd
    const int g = lane >> 2, t4 = lane & 3;
#pragma unroll
    for (int mt = 0; mt < 2; mt++) {
        float sA = 0.f, sB = 0.f;
#pragma unroll
        for (int nt = 0; nt < 8; nt++) {
            int c0 = n0 + wn * 64 + nt * 8 + 2 * t4;
            float b1a = b1[c0], b1b = b1[c0 + 1];
            float w2a = W2[c0], w2b = W2[c0 + 1];
            sA += fast_tanh(acc[mt][nt][0] + b1a) * w2a + fast_tanh(acc[mt][nt][1] + b1b) * w2b;
            sB += fast_tanh(acc[mt][nt][2] + b1a) * w2a + fast_tanh(acc[mt][nt][3] + b1b) * w2b;
        }
        sA += __shfl_xor_sync(0xFFFFFFFF, sA, 1);
        sA += __shfl_xor_sync(0xFFFFFFFF, sA, 2);
        sB += __shfl_xor_sync(0xFFFFFFFF, sB, 1);
        sB += __shfl_xor_sync(0xFFFFFFFF, sB, 2);
        if (t4 == 0) {
            int r = m0 + wm * 32 + mt * 16 + g;
            atomicAdd(&g_a[r], sA);
            atomicAdd(&g_a[r + 8], sB);
        }
    }
}

// ---------------- pool (with in-block softmax over W) ----------------
__global__ void pool_kernel() {
    int b = blockIdx.y;
    int f = blockIdx.x * 256 + threadIdx.x;
    int t = threadIdx.x;
    __shared__ float sat[NW];
    __shared__ float red[NW];
    // in-block softmax of g_a[b, :] (128 values, L2-hot)
    float v = 0.f;
    if (t < NW) { v = g_a[b * NW + t]; red[t] = v; }
    __syncthreads();
    for (int s = 64; s > 0; s >>= 1) { if (t < s) red[t] = fmaxf(red[t], red[t + s]); __syncthreads(); }
    float m = red[0];
    __syncthreads();
    float e = 0.f;
    if (t < NW) { e = expf(v - m); red[t] = e; }
    __syncthreads();
    for (int s = 64; s > 0; s >>= 1) { if (t < s) red[t] += red[t + s]; __syncthreads(); }
    if (t < NW) sat[t] = e / red[0];
    __syncthreads();
    if (f >= FEAT) return;
    float acc = 0.f;
    const __half* bh = g_bag + (size_t)b * NW * FEATP + f;
#pragma unroll 4
    for (int w = 0; w < NW; w++)
        acc += sat[w] * __half2float(bh[(size_t)w * FEATP]);
    g_bagz0[b * FEATP + f] = acc;
}

// ---------------- batchnorms (also inits q/k2/v2/t1 bias accumulators) ----
__global__ void bn_kernel(const float* __restrict__ cc,
                          const float* __restrict__ bn_g, const float* __restrict__ bn_b,
                          const float* __restrict__ bn2_g, const float* __restrict__ bn2_b,
                          const float* __restrict__ bq, const float* __restrict__ bk,
                          const float* __restrict__ bc1) {
    // strided init of downstream accumulator buffers
    int gt = blockIdx.x * 256 + threadIdx.x;
    int nthr = gridDim.x * 256;
    for (int idx = gt; idx < NB * HH; idx += nthr) g_q[idx] = bq[idx & (HH - 1)];
    for (int idx = gt; idx < 2 * HH; idx += nthr) { g_k2[idx] = bk[idx & (HH - 1)]; g_v2[idx] = bq[idx & (HH - 1)]; }
    for (int idx = gt; idx < NB * DD; idx += nthr) g_t1[idx] = bc1[idx & (DD - 1)];

    int f = gt;
    if (f >= FEAT) return;
    float mu = 0.f;
    for (int b = 0; b < NB; b++) mu += g_bagz0[b * FEATP + f];
    mu *= (1.f / NB);
    float var = 0.f;
    for (int b = 0; b < NB; b++) { float d = g_bagz0[b * FEATP + f] - mu; var += d * d; }
    var *= (1.f / NB);
    float inv = rsqrtf(var + 1e-5f);
    float g = bn_g[f], bt = bn_b[f];
    for (int b = 0; b < NB; b++)
        g_bagz[b * FEATP + f] = (g_bagz0[b * FEATP + f] - mu) * inv * g + bt;
    float c0 = cc[f], c1 = cc[FEAT + f];
    float mu2 = 0.5f * (c0 + c1);
    float d0 = c0 - mu2, d1 = c1 - mu2;
    float inv2 = rsqrtf(0.5f * (d0 * d0 + d1 * d1) + 1e-5f);
    float g2 = bn2_g[f], b2v = bn2_b[f];
    g_ccn[f] = d0 * inv2 * g2 + b2v;
    g_ccn[FEATP + f] = d1 * inv2 * g2 + b2v;
}

// ---------------- skinny GEMM: C[M,N] += A[M,K] @ B[K,N], split-K atomics ----
template <int M>
__global__ __launch_bounds__(256) void skinny_kernel(int selA, int lda,
                                                     const float* __restrict__ B, int ldb,
                                                     int selC, int K, int N) {
    const float* A = (selA == 0) ? g_bagz : (selA == 1) ? g_ccn : g_fcx;
    float* C = (selC == 0) ? g_q : (selC == 1) ? g_k2 : (selC == 2) ? g_v2 : g_t1;
    __shared__ float sA[M][33];
    int tid = threadIdx.x;
    int col = blockIdx.x * 256 + tid;
    int nsplit = gridDim.y;
    int len = (K + nsplit - 1) / nsplit;
    int k0 = blockIdx.y * len;
    int kend = min(K, k0 + len);
    float acc[M];
#pragma unroll
    for (int m = 0; m < M; m++) acc[m] = 0.f;
    for (int kb = k0; kb < kend; kb += 32) {
        int kmax = min(32, kend - kb);
        for (int idx = tid; idx < M * 32; idx += 256) {
            int m = idx >> 5, kk = idx & 31;
            sA[m][kk] = (kk < kmax) ? A[(size_t)m * lda + kb + kk] : 0.f;
        }
        __syncthreads();
        if (col < N) {
            const float* Bp = B + (size_t)kb * ldb + col;
            int kk = 0;
            for (; kk + 4 <= kmax; kk += 4) {
                float bv0 = Bp[0];
                float bv1 = Bp[(size_t)ldb];
                float bv2 = Bp[2 * (size_t)ldb];
                float bv3 = Bp[3 * (size_t)ldb];
                Bp += 4 * (size_t)ldb;
#pragma unroll
                for (int m = 0; m < M; m++) acc[m] += sA[m][kk] * bv0;
#pragma unroll
                for (int m = 0; m < M; m++) acc[m] += sA[m][kk + 1] * bv1;
#pragma unroll
                for (int m = 0; m < M; m++) acc[m] += sA[m][kk + 2] * bv2;
#pragma unroll
                for (int m = 0; m < M; m++) acc[m] += sA[m][kk + 3] * bv3;
            }
            for (; kk < kmax; kk++) {
                float bv = Bp[0]; Bp += (size_t)ldb;
#pragma unroll
                for (int m = 0; m < M; m++) acc[m] += sA[m][kk] * bv;
            }
        }
        __syncthreads();
    }
    if (col < N) {
#pragma unroll
        for (int m = 0; m < M; m++) atomicAdd(&C[(size_t)m * N + col], acc[m]);
    }
}

// ---------------- merged k/v skinny: k2 += ccn@Wk, v2 += ccn@Wq ----------------
__global__ __launch_bounds__(256) void kv_kernel(const float* __restrict__ Wk,
                                                 const float* __restrict__ Wq) {
    __shared__ float sA[2][33];
    int tid = threadIdx.x;
    int col = blockIdx.x * 256 + tid;   // < HH
    int nsplit = gridDim.y;
    int len = (FEAT + nsplit - 1) / nsplit;
    int k0 = blockIdx.y * len;
    int kend = min(FEAT, k0 + len);
    float ak0 = 0.f, ak1 = 0.f, av0 = 0.f, av1 = 0.f;
    for (int kb = k0; kb < kend; kb += 32) {
        int kmax = min(32, kend - kb);
        if (tid < 64) {
            int m = tid >> 5, kk = tid & 31;
            sA[m][kk] = (kk < kmax) ? g_ccn[(size_t)m * FEATP + kb + kk] : 0.f;
        }
        __syncthreads();
        const float* Kp = Wk + (size_t)kb * HH + col;
        const float* Qp = Wq + (size_t)kb * HH + col;
        int kk = 0;
        for (; kk + 2 <= kmax; kk += 2) {
            float k0v = Kp[0], k1v = Kp[HH];
            float q0v = Qp[0], q1v = Qp[HH];
            Kp += 2 * HH; Qp += 2 * HH;
            ak0 += sA[0][kk] * k0v; ak1 += sA[1][kk] * k0v;
            av0 += sA[0][kk] * q0v; av1 += sA[1][kk] * q0v;
            ak0 += sA[0][kk + 1] * k1v; ak1 += sA[1][kk + 1] * k1v;
            av0 += sA[0][kk + 1] * q1v; av1 += sA[1][kk + 1] * q1v;
        }
        for (; kk < kmax; kk++) {
            float kv = Kp[0], qv = Qp[0]; Kp += HH; Qp += HH;
            ak0 += sA[0][kk] * kv; ak1 += sA[1][kk] * kv;
            av0 += sA[0][kk] * qv; av1 += sA[1][kk] * qv;
        }
        __syncthreads();
    }
    atomicAdd(&g_k2[col], ak0);
    atomicAdd(&g_k2[HH + col], ak1);
    atomicAdd(&g_v2[col], av0);
    atomicAdd(&g_v2[HH + col], av1);
}

// ---------------- cross attention ----------------
__global__ void cross_kernel() {
    __shared__ float sQK[64][2];
    __shared__ float sac[64][2];
    int t = threadIdx.x;  // 256
    if (t < 128) {
        int b = t >> 1, r = t & 1;
        const float* qp = g_q + b * HH;
        const float* kp = g_k2 + r * HH;
        float acc = 0.f;
        for (int d = 0; d < HH; d++) acc += qp[d] * kp[d];
        sQK[b][r] = acc * (1.0f / 32.0f);
    }
    __syncthreads();
    if (t < 64) {
        float x0 = sQK[t][0], x1 = sQK[t][1];
        float m = fmaxf(x0, x1);
        float e0 = expf(x0 - m), e1 = expf(x1 - m);
        float inv = 1.f / (e0 + e1);
        sac[t][0] = e0 * inv; sac[t][1] = e1 * inv;
    }
    __syncthreads();
    for (int idx = t; idx < NB * HH; idx += 256) {
        int b = idx >> 10, d = idx & 1023;
        g_fcx[idx] = sac[b][0] * g_v2[d] + sac[b][1] * g_v2[HH + d];
    }
}

// ---------------- classifier head ----------------
__global__ void final_kernel(const float* __restrict__ Wc2, const float* __restrict__ bc2,
                             float* __restrict__ out, int out_size) {
    int b = blockIdx.x, t = threadIdx.x;
    float acc = 0.f;
    for (int d = t; d < DD; d += 256) acc += fmaxf(g_t1[b * DD + d], 0.f) * Wc2[d];
    __shared__ float red[256];
    red[t] = acc; __syncthreads();
    for (int s = 128; s > 0; s >>= 1) { if (t < s) red[t] += red[t + s]; __syncthreads(); }
    if (t == 0) {
        float y = 1.f / (1.f + expf(-(red[0] + bc2[0])));
        out[b] = y;
        if (64 + b < out_size) out[64 + b] = (y >= 0.5f) ? 1.f : 0.f;
    }
}

// ---------------- launch ----------------
extern "C" void kernel_launch(void* const* d_in, const int* in_sizes, int n_in,
                              void* d_out, int out_size) {
    const float* FC    = (const float*)d_in[0];
    const float* cc    = (const float*)d_in[1];
    const float* W1    = (const float*)d_in[2];
    const float* b1    = (const float*)d_in[3];
    const float* W2    = (const float*)d_in[4];
    const float* b2    = (const float*)d_in[5];
    const float* bn_g  = (const float*)d_in[6];
    const float* bn_b  = (const float*)d_in[7];
    const float* bn2_g = (const float*)d_in[8];
    const float* bn2_b = (const float*)d_in[9];
    const float* Wq    = (const float*)d_in[10];
    const float* bq    = (const float*)d_in[11];
    const float* Wk    = (const float*)d_in[12];
    const float* bk    = (const float*)d_in[13];
    const float* Wc1   = (const float*)d_in[14];
    const float* bc1   = (const float*)d_in[15];
    const float* Wc2   = (const float*)d_in[16];
    const float* bc2   = (const float*)d_in[17];
    float* out = (float*)d_out;

    cudaFuncSetAttribute(gemm_mma_kernel, cudaFuncAttributeMaxDynamicSharedMemorySize, GEMM_SMEM);

    init_off_kernel<<<ROI - 1, 128>>>();                                   // 1
    gather_kernel<<<dim3((FEATP + 255) / 256, BW), 256>>>(FC);             // 2
    w1t_kernel<<<dim3(FEATP / 32, DD / 32), dim3(32, 8)>>>(W1, b2);        // 3
    gemm_mma_kernel<<<dim3(8, 64), 256, GEMM_SMEM>>>(b1, W2);              // 4 (ncu slot)
    pool_kernel<<<dim3((FEAT + 255) / 256, NB), 256>>>();
    bn_kernel<<<(FEAT + 255) / 256, 256>>>(cc, bn_g, bn_b, bn2_g, bn2_b, bq, bk, bc1);
    skinny_kernel<64><<<dim3(4, 26), 256>>>(0, FEATP, Wq, HH, 0, FEAT, HH);
    kv_kernel<<<dim3(4, 8), 256>>>(Wk, Wq);
    cross_kernel<<<1, 256>>>();
    skinny_kernel<64><<<dim3(4, 8), 256>>>(2, HH, Wc1, DD, 3, HH, DD);
    skinny_kernel<64><<<dim3(4, 26), 256>>>(0, FEATP, Wc1 + (size_t)HH * DD, DD, 3, FEAT, DD);
    final_kernel<<<NB, 256>>>(Wc2, bc2, out, out_size);
}

// round 11
// speedup vs baseline: 1.2186x; 1.2186x over previous
#include <cuda_runtime.h>
#include <cuda_fp16.h>
#include <math.h>
#include <stdint.h>

#define ROI   116
#define FEAT  6670      // ROI*(ROI-1)/2
#define FEATP 6720      // padded to multiple of 64
#define NB    64        // batch
#define NW    128       // bags per batch
#define BW    8192      // NB*NW
#define DD    1024
#define HH    1024
#define NSTG64 (FEATP / 64)  // 105 K-stages of 64

// ---------------- scratch (device globals; no allocation) ----------------
__device__ __align__(16) __half g_bag[(size_t)BW * FEATP];   // 110 MB
__device__ __align__(16) __half g_w1th[(size_t)DD * FEATP];  // 13.8 MB  [N][K]
__device__ __align__(16) int g_off[FEATP];
__device__ float g_a[BW];
__device__ float g_att[BW];
__device__ float g_bagz0[NB * FEATP];
__device__ float g_bagz[NB * FEATP];
__device__ float g_ccn[2 * FEATP];
__device__ float g_q[NB * HH];
__device__ float g_k2[2 * HH];
__device__ float g_v2[2 * HH];
__device__ float g_fcx[NB * HH];
__device__ float g_t1[NB * DD];

// ---------------- PTX helpers (generic, sm_80-level) ----------------
__device__ __forceinline__ uint32_t smem_u32(const void* p) {
    uint32_t a;
    asm("{ .reg .u64 t; cvta.to.shared.u64 t, %1; cvt.u32.u64 %0, t; }" : "=r"(a) : "l"(p));
    return a;
}
#define CP_ASYNC16(dst, src) \
    asm volatile("cp.async.cg.shared.global [%0], [%1], 16;" \
                 :: "r"(dst), "l"(src) : "memory")
#define CP_COMMIT() asm volatile("cp.async.commit_group;" ::: "memory")
#define CP_WAIT(n)  asm volatile("cp.async.wait_group %0;" :: "n"(n) : "memory")

__device__ __forceinline__ void ldm_x4(uint32_t& r0, uint32_t& r1, uint32_t& r2, uint32_t& r3,
                                       uint32_t addr) {
    asm volatile("ldmatrix.sync.aligned.m8n8.x4.shared.b16 {%0,%1,%2,%3}, [%4];"
                 : "=r"(r0), "=r"(r1), "=r"(r2), "=r"(r3) : "r"(addr));
}
__device__ __forceinline__ void mma16816(float* c, const uint32_t* a, const uint32_t* b) {
    asm volatile(
        "mma.sync.aligned.m16n8k16.row.col.f32.f16.f16.f32 "
        "{%0,%1,%2,%3}, {%4,%5,%6,%7}, {%8,%9}, {%0,%1,%2,%3};"
        : "+f"(c[0]), "+f"(c[1]), "+f"(c[2]), "+f"(c[3])
        : "r"(a[0]), "r"(a[1]), "r"(a[2]), "r"(a[3]), "r"(b[0]), "r"(b[1]));
}
__device__ __forceinline__ float fast_tanh(float x) {
    float e = __expf(2.0f * x);
    return 1.0f - 2.0f / (e + 1.0f);
}

// ---------------- triu index table (padded to FEATP with 0) ----------------
__global__ void init_off_kernel() {
    int i = blockIdx.x;                      // 0..ROI-1
    if (i == ROI - 1) {                      // padding block
        for (int f = FEAT + threadIdx.x; f < FEATP; f += blockDim.x) g_off[f] = 0;
        return;
    }
    int base = i * (ROI - 1) - i * (i - 1) / 2;
    int cnt = ROI - 1 - i;
    for (int jj = threadIdx.x; jj < cnt; jj += blockDim.x)
        g_off[base + jj] = i * ROI + (i + 1 + jj);
}

// ---------------- gather -> fp16 (4 features per thread) ----------------
__global__ void gather_kernel(const float* __restrict__ FC) {
    int bw = blockIdx.y;
    int f0 = (blockIdx.x * 256 + threadIdx.x) * 4;
    if (f0 >= FEATP) return;
    const float* src = FC + (size_t)bw * (ROI * ROI);
    int4 off = *reinterpret_cast<const int4*>(g_off + f0);
    __half h0 = (f0 + 0 < FEAT) ? __float2half_rn(src[off.x]) : __half(0.f);
    __half h1 = (f0 + 1 < FEAT) ? __float2half_rn(src[off.y]) : __half(0.f);
    __half h2 = (f0 + 2 < FEAT) ? __float2half_rn(src[off.z]) : __half(0.f);
    __half h3 = (f0 + 3 < FEAT) ? __float2half_rn(src[off.w]) : __half(0.f);
    __half2* dst = reinterpret_cast<__half2*>(g_bag + (size_t)bw * FEATP + f0);
    dst[0] = __halves2half2(h0, h1);
    dst[1] = __halves2half2(h2, h3);
}

// ---------------- W1 -> W1T fp16 ([N][K], padded); also inits g_a = b2 ----
__global__ void w1t_kernel(const float* __restrict__ W1, const float* __restrict__ b2) {
    __shared__ float t[32][33];
    int kb = blockIdx.x * 32, nb = blockIdx.y * 32;
    int tx = threadIdx.x, ty = threadIdx.y;
    if (blockIdx.x == 0 && blockIdx.y == 0) {
        int tid = ty * 32 + tx;
        float v = b2[0];
        for (int i = tid; i < BW; i += 256) g_a[i] = v;
    }
#pragma unroll
    for (int i = 0; i < 32; i += 8) {
        int k = kb + ty + i;
        t[ty + i][tx] = (k < FEAT) ? W1[(size_t)k * DD + nb + tx] : 0.f;
    }
    __syncthreads();
#pragma unroll
    for (int i = 0; i < 32; i += 8) {
        float v = t[tx][ty + i];
        g_w1th[(size_t)(nb + ty + i) * FEATP + kb + tx] = __float2half_rn(v);
    }
}

// ---------------- init biases into accumulator buffers (post-GEMM ones) ----
__global__ void init_misc_kernel(const float* __restrict__ bq,
                                 const float* __restrict__ bk,
                                 const float* __restrict__ bc1) {
    int idx = blockIdx.x * 256 + threadIdx.x;
    if (idx < NB * HH) { g_q[idx] = bq[idx & (HH - 1)]; return; }
    idx -= NB * HH;
    if (idx < 2 * HH) { g_k2[idx] = bk[idx & (HH - 1)]; return; }
    idx -= 2 * HH;
    if (idx < 2 * HH) { g_v2[idx] = bq[idx & (HH - 1)]; return; }
    idx -= 2 * HH;
    if (idx < NB * DD) { g_t1[idx] = bc1[idx & (DD - 1)]; return; }
}

// ---------------- HMMA GEMM: S = bag @ W1T^T (fp16), fused tanh/W2 epi ----
// CTA 128x128, 8 warps (4Mx2N), warp tile 32x64. K-stage 64, 3-stage
// pipeline (CP_WAIT(1)), one __syncthreads per stage. rows 144B.
#define LDA       144
#define TILE_B    18432               // 128 rows x 144B
#define STAGE_B   (2 * TILE_B)        // A + B = 36864
#define GEMM_SMEM (3 * STAGE_B)       // 110592

__device__ __forceinline__ void load_stage(uint32_t sdst, int k0, int m0, int n0, int tid) {
    int row = tid >> 1;
    int cb = (tid & 1) * 64;          // byte offset within 128B row half
    uint32_t so = sdst + row * LDA + cb;
    size_t ga = ((size_t)(m0 + row) * FEATP + k0) * 2 + cb;
    size_t gb = ((size_t)(n0 + row) * FEATP + k0) * 2 + cb;
    unsigned long long pa = __cvta_generic_to_global((const char*)g_bag + ga);
    unsigned long long pb = __cvta_generic_to_global((const char*)g_w1th + gb);
    CP_ASYNC16(so,      pa);      CP_ASYNC16(so + 16, pa + 16);
    CP_ASYNC16(so + 32, pa + 32); CP_ASYNC16(so + 48, pa + 48);
    so += TILE_B;
    CP_ASYNC16(so,      pb);      CP_ASYNC16(so + 16, pb + 16);
    CP_ASYNC16(so + 32, pb + 32); CP_ASYNC16(so + 48, pb + 48);
}

__global__ __launch_bounds__(256, 2) void gemm_mma_kernel(const float* __restrict__ b1,
                                                          const float* __restrict__ W2) {
    extern __shared__ char sm[];
    const uint32_t sbase = smem_u32(sm);
    const int tid = threadIdx.x, lane = tid & 31, wid = tid >> 5;
    const int wm = wid & 3, wn = wid >> 2;        // 4 M-warps x 2 N-warps
    const int n0 = blockIdx.x * 128, m0 = blockIdx.y * 128;

    float acc[2][8][4];
#pragma unroll
    for (int mt = 0; mt < 2; mt++)
#pragma unroll
        for (int nt = 0; nt < 8; nt++)
#pragma unroll
            for (int c = 0; c < 4; c++) acc[mt][nt][c] = 0.f;

    load_stage(sbase, 0, m0, n0, tid);             CP_COMMIT();
    load_stage(sbase + STAGE_B, 64, m0, n0, tid);  CP_COMMIT();

    const uint32_t aRowOfs = (uint32_t)(wm * 32 + ((lane >> 3) & 1) * 8 + (lane & 7)) * LDA
                           + (uint32_t)(lane >> 4) * 16;
    const uint32_t bRowOfs = (uint32_t)(wn * 64 + (lane >> 4) * 8 + (lane & 7)) * LDA
                           + (uint32_t)((lane >> 3) & 1) * 16;

    int slot = 0;
    for (int i = 0; i < NSTG64; i++) {
        if (i + 1 < NSTG64) { CP_WAIT(1); } else { CP_WAIT(0); }
        __syncthreads();
        if (i + 2 < NSTG64) {
            int ns = slot + 2; if (ns >= 3) ns -= 3;
            load_stage(sbase + (uint32_t)ns * STAGE_B, (i + 2) * 64, m0, n0, tid);
            CP_COMMIT();
        }
        const uint32_t st = sbase + (uint32_t)slot * STAGE_B;
#pragma unroll
        for (int kk = 0; kk < 4; kk++) {
            uint32_t aH[2][4], bb[8][2];
#pragma unroll
            for (int mt = 0; mt < 2; mt++)
                ldm_x4(aH[mt][0], aH[mt][1], aH[mt][2], aH[mt][3],
                       st + aRowOfs + (uint32_t)mt * 16 * LDA + kk * 32);
#pragma unroll
            for (int p = 0; p < 4; p++)
                ldm_x4(bb[2 * p][0], bb[2 * p][1], bb[2 * p + 1][0], bb[2 * p + 1][1],
                       st + TILE_B + bRowOfs + (uint32_t)p * 16 * LDA + kk * 32);
#pragma unroll
            for (int mt = 0; mt < 2; mt++)
#pragma unroll
                for (int nt = 0; nt < 8; nt++) mma16816(acc[mt][nt], aH[mt], bb[nt]);
        }
        if (++slot == 3) slot = 0;
    }

    // epilogue: per-row sum over n of tanh(S + b1)*W2, reduce, atomicAdd
    const int g = lane >> 2, t4 = lane & 3;
#pragma unroll
    for (int mt = 0; mt < 2; mt++) {
        float sA = 0.f, sB = 0.f;
#pragma unroll
        for (int nt = 0; nt < 8; nt++) {
            int c0 = n0 + wn * 64 + nt * 8 + 2 * t4;
            float b1a = b1[c0], b1b = b1[c0 + 1];
            float w2a = W2[c0], w2b = W2[c0 + 1];
            sA += fast_tanh(acc[mt][nt][0] + b1a) * w2a + fast_tanh(acc[mt][nt][1] + b1b) * w2b;
            sB += fast_tanh(acc[mt][nt][2] + b1a) * w2a + fast_tanh(acc[mt][nt][3] + b1b) * w2b;
        }
        sA += __shfl_xor_sync(0xFFFFFFFF, sA, 1);
        sA += __shfl_xor_sync(0xFFFFFFFF, sA, 2);
        sB += __shfl_xor_sync(0xFFFFFFFF, sB, 1);
        sB += __shfl_xor_sync(0xFFFFFFFF, sB, 2);
        if (t4 == 0) {
            int r = m0 + wm * 32 + mt * 16 + g;
            atomicAdd(&g_a[r], sA);
            atomicAdd(&g_a[r + 8], sB);
        }
    }
}

// ---------------- softmax over W per batch ----------------
__global__ void softmax_kernel() {
    int b = blockIdx.x, t = threadIdx.x;  // 128 threads
    __shared__ float sv[128];
    float v = g_a[b * NW + t];
    sv[t] = v; __syncthreads();
    for (int s = 64; s > 0; s >>= 1) { if (t < s) sv[t] = fmaxf(sv[t], sv[t + s]); __syncthreads(); }
    float m = sv[0]; __syncthreads();
    float e = expf(v - m);
    sv[t] = e; __syncthreads();
    for (int s = 64; s > 0; s >>= 1) { if (t < s) sv[t] += sv[t + s]; __syncthreads(); }
    g_att[b * NW + t] = e / sv[0];
}

// ---------------- attention pool ----------------
__global__ void pool_kernel() {
    int b = blockIdx.y;
    int f = blockIdx.x * 256 + threadIdx.x;
    __shared__ float sat[NW];
    if (threadIdx.x < NW) sat[threadIdx.x] = g_att[b * NW + threadIdx.x];
    __syncthreads();
    if (f >= FEAT) return;
    float acc = 0.f;
    const __half* bh = g_bag + (size_t)b * NW * FEATP + f;
#pragma unroll 4
    for (int w = 0; w < NW; w++)
        acc += sat[w] * __half2float(bh[(size_t)w * FEATP]);
    g_bagz0[b * FEATP + f] = acc;
}

// ---------------- batchnorms ----------------
__global__ void bn_kernel(const float* __restrict__ cc,
                          const float* __restrict__ bn_g, const float* __restrict__ bn_b,
                          const float* __restrict__ bn2_g, const float* __restrict__ bn2_b) {
    int f = blockIdx.x * 256 + threadIdx.x;
    if (f >= FEAT) return;
    float mu = 0.f;
    for (int b = 0; b < NB; b++) mu += g_bagz0[b * FEATP + f];
    mu *= (1.f / NB);
    float var = 0.f;
    for (int b = 0; b < NB; b++) { float d = g_bagz0[b * FEATP + f] - mu; var += d * d; }
    var *= (1.f / NB);
    float inv = rsqrtf(var + 1e-5f);
    float g = bn_g[f], bt = bn_b[f];
    for (int b = 0; b < NB; b++)
        g_bagz[b * FEATP + f] = (g_bagz0[b * FEATP + f] - mu) * inv * g + bt;
    float c0 = cc[f], c1 = cc[FEAT + f];
    float mu2 = 0.5f * (c0 + c1);
    float d0 = c0 - mu2, d1 = c1 - mu2;
    float inv2 = rsqrtf(0.5f * (d0 * d0 + d1 * d1) + 1e-5f);
    float g2 = bn2_g[f], b2v = bn2_b[f];
    g_ccn[f] = d0 * inv2 * g2 + b2v;
    g_ccn[FEATP + f] = d1 * inv2 * g2 + b2v;
}

// ---------------- skinny GEMM: C[M,N] += A[M,K] @ B[K,N], split-K atomics ----
template <int M>
__global__ __launch_bounds__(256) void skinny_kernel(int selA, int lda,
                                                     const float* __restrict__ B, int ldb,
                                                     int selC, int K, int N) {
    const float* A = (selA == 0) ? g_bagz : (selA == 1) ? g_ccn : g_fcx;
    float* C = (selC == 0) ? g_q : (selC == 1) ? g_k2 : (selC == 2) ? g_v2 : g_t1;
    __shared__ float sA[M][33];
    int tid = threadIdx.x;
    int col = blockIdx.x * 256 + tid;
    int nsplit = gridDim.y;
    int len = (K + nsplit - 1) / nsplit;
    int k0 = blockIdx.y * len;
    int kend = min(K, k0 + len);
    float acc[M];
#pragma unroll
    for (int m = 0; m < M; m++) acc[m] = 0.f;
    for (int kb = k0; kb < kend; kb += 32) {
        int kmax = min(32, kend - kb);
        for (int idx = tid; idx < M * 32; idx += 256) {
            int m = idx >> 5, kk = idx & 31;
            sA[m][kk] = (kk < kmax) ? A[(size_t)m * lda + kb + kk] : 0.f;
        }
        __syncthreads();
        if (col < N) {
            const float* Bp = B + (size_t)kb * ldb + col;
            int kk = 0;
            for (; kk + 4 <= kmax; kk += 4) {
                float bv0 = Bp[0];
                float bv1 = Bp[(size_t)ldb];
                float bv2 = Bp[2 * (size_t)ldb];
                float bv3 = Bp[3 * (size_t)ldb];
                Bp += 4 * (size_t)ldb;
#pragma unroll
                for (int m = 0; m < M; m++) acc[m] += sA[m][kk] * bv0;
#pragma unroll
                for (int m = 0; m < M; m++) acc[m] += sA[m][kk + 1] * bv1;
#pragma unroll
                for (int m = 0; m < M; m++) acc[m] += sA[m][kk + 2] * bv2;
#pragma unroll
                for (int m = 0; m < M; m++) acc[m] += sA[m][kk + 3] * bv3;
            }
            for (; kk < kmax; kk++) {
                float bv = Bp[0]; Bp += (size_t)ldb;
#pragma unroll
                for (int m = 0; m < M; m++) acc[m] += sA[m][kk] * bv;
            }
        }
        __syncthreads();
    }
    if (col < N) {
#pragma unroll
        for (int m = 0; m < M; m++) atomicAdd(&C[(size_t)m * N + col], acc[m]);
    }
}

// ---------------- merged k/v skinny: k2 += ccn@Wk, v2 += ccn@Wq ----------------
__global__ __launch_bounds__(256) void kv_kernel(const float* __restrict__ Wk,
                                                 const float* __restrict__ Wq) {
    __shared__ float sA[2][33];
    int tid = threadIdx.x;
    int col = blockIdx.x * 256 + tid;   // < HH
    int nsplit = gridDim.y;
    int len = (FEAT + nsplit - 1) / nsplit;
    int k0 = blockIdx.y * len;
    int kend = min(FEAT, k0 + len);
    float ak0 = 0.f, ak1 = 0.f, av0 = 0.f, av1 = 0.f;
    for (int kb = k0; kb < kend; kb += 32) {
        int kmax = min(32, kend - kb);
        if (tid < 64) {
            int m = tid >> 5, kk = tid & 31;
            sA[m][kk] = (kk < kmax) ? g_ccn[(size_t)m * FEATP + kb + kk] : 0.f;
        }
        __syncthreads();
        const float* Kp = Wk + (size_t)kb * HH + col;
        const float* Qp = Wq + (size_t)kb * HH + col;
        int kk = 0;
        for (; kk + 2 <= kmax; kk += 2) {
            float k0v = Kp[0], k1v = Kp[HH];
            float q0v = Qp[0], q1v = Qp[HH];
            Kp += 2 * HH; Qp += 2 * HH;
            ak0 += sA[0][kk] * k0v; ak1 += sA[1][kk] * k0v;
            av0 += sA[0][kk] * q0v; av1 += sA[1][kk] * q0v;
            ak0 += sA[0][kk + 1] * k1v; ak1 += sA[1][kk + 1] * k1v;
            av0 += sA[0][kk + 1] * q1v; av1 += sA[1][kk + 1] * q1v;
        }
        for (; kk < kmax; kk++) {
            float kv = Kp[0], qv = Qp[0]; Kp += HH; Qp += HH;
            ak0 += sA[0][kk] * kv; ak1 += sA[1][kk] * kv;
            av0 += sA[0][kk] * qv; av1 += sA[1][kk] * qv;
        }
        __syncthreads();
    }
    atomicAdd(&g_k2[col], ak0);
    atomicAdd(&g_k2[HH + col], ak1);
    atomicAdd(&g_v2[col], av0);
    atomicAdd(&g_v2[HH + col], av1);
}

// ---------------- cross attention ----------------
__global__ void cross_kernel() {
    __shared__ float sQK[64][2];
    __shared__ float sac[64][2];
    int t = threadIdx.x;  // 256
    if (t < 128) {
        int b = t >> 1, r = t & 1;
        const float* qp = g_q + b * HH;
        const float* kp = g_k2 + r * HH;
        float acc = 0.f;
        for (int d = 0; d < HH; d++) acc += qp[d] * kp[d];
        sQK[b][r] = acc * (1.0f / 32.0f);
    }
    __syncthreads();
    if (t < 64) {
        float x0 = sQK[t][0], x1 = sQK[t][1];
        float m = fmaxf(x0, x1);
        float e0 = expf(x0 - m), e1 = expf(x1 - m);
        float inv = 1.f / (e0 + e1);
        sac[t][0] = e0 * inv; sac[t][1] = e1 * inv;
    }
    __syncthreads();
    for (int idx = t; idx < NB * HH; idx += 256) {
        int b = idx >> 10, d = idx & 1023;
        g_fcx[idx] = sac[b][0] * g_v2[d] + sac[b][1] * g_v2[HH + d];
    }
}

// ---------------- classifier head ----------------
__global__ void final_kernel(const float* __restrict__ Wc2, const float* __restrict__ bc2,
                             float* __restrict__ out, int out_size) {
    int b = blockIdx.x, t = threadIdx.x;
    float acc = 0.f;
    for (int d = t; d < DD; d += 256) acc += fmaxf(g_t1[b * DD + d], 0.f) * Wc2[d];
    __shared__ float red[256];
    red[t] = acc; __syncthreads();
    for (int s = 128; s > 0; s >>= 1) { if (t < s) red[t] += red[t + s]; __syncthreads(); }
    if (t == 0) {
        float y = 1.f / (1.f + expf(-(red[0] + bc2[0])));
        out[b] = y;
        if (64 + b < out_size) out[64 + b] = (y >= 0.5f) ? 1.f : 0.f;
    }
}

// ---------------- launch ----------------
extern "C" void kernel_launch(void* const* d_in, const int* in_sizes, int n_in,
                              void* d_out, int out_size) {
    const float* FC    = (const float*)d_in[0];
    const float* cc    = (const float*)d_in[1];
    const float* W1    = (const float*)d_in[2];
    const float* b1    = (const float*)d_in[3];
    const float* W2    = (const float*)d_in[4];
    const float* b2    = (const float*)d_in[5];
    const float* bn_g  = (const float*)d_in[6];
    const float* bn_b  = (const float*)d_in[7];
    const float* bn2_g = (const float*)d_in[8];
    const float* bn2_b = (const float*)d_in[9];
    const float* Wq    = (const float*)d_in[10];
    const float* bq    = (const float*)d_in[11];
    const float* Wk    = (const float*)d_in[12];
    const float* bk    = (const float*)d_in[13];
    const float* Wc1   = (const float*)d_in[14];
    const float* bc1   = (const float*)d_in[15];
    const float* Wc2   = (const float*)d_in[16];
    const float* bc2   = (const float*)d_in[17];
    float* out = (float*)d_out;

    cudaFuncSetAttribute(gemm_mma_kernel, cudaFuncAttributeMaxDynamicSharedMemorySize, GEMM_SMEM);

    init_off_kernel<<<ROI, 128>>>();
    gather_kernel<<<dim3(7, BW), 256>>>(FC);
    w1t_kernel<<<dim3(FEATP / 32, DD / 32), dim3(32, 8)>>>(W1, b2);
    gemm_mma_kernel<<<dim3(8, 64), 256, GEMM_SMEM>>>(b1, W2);              // ncu slot
    init_misc_kernel<<<(NB * HH + 4 * HH + NB * DD + 255) / 256, 256>>>(bq, bk, bc1);
    softmax_kernel<<<NB, 128>>>();
    pool_kernel<<<dim3((FEAT + 255) / 256, NB), 256>>>();
    bn_kernel<<<(FEAT + 255) / 256, 256>>>(cc, bn_g, bn_b, bn2_g, bn2_b);
    skinny_kernel<64><<<dim3(4, 104), 256>>>(0, FEATP, Wq, HH, 0, FEAT, HH);
    kv_kernel<<<dim3(4, 16), 256>>>(Wk, Wq);
    cross_kernel<<<1, 256>>>();
    skinny_kernel<64><<<dim3(4, 16), 256>>>(2, HH, Wc1, DD, 3, HH, DD);
    skinny_kernel<64><<<dim3(4, 104), 256>>>(0, FEATP, Wc1 + (size_t)HH * DD, DD, 3, FEAT, DD);
    final_kernel<<<NB, 256>>>(Wc2, bc2, out, out_size);
}

// round 12
// speedup vs baseline: 1.2473x; 1.0236x over previous
#include <cuda_runtime.h>
#include <cuda_fp16.h>
#include <math.h>
#include <stdint.h>

#define ROI   116
#define FEAT  6670      // ROI*(ROI-1)/2
#define FEATP 6720      // padded to multiple of 64
#define NB    64        // batch
#define NW    128       // bags per batch
#define BW    8192      // NB*NW
#define DD    1024
#define HH    1024
#define NSTG64 (FEATP / 64)  // 105 K-stages of 64

// ---------------- scratch (device globals; no allocation) ----------------
__device__ __align__(16) __half g_bag[(size_t)BW * FEATP];   // 110 MB
__device__ __align__(16) __half g_w1th[(size_t)DD * FEATP];  // 13.8 MB  [N][K]
__device__ __align__(16) int g_off[FEATP];
__device__ float g_a[BW];
__device__ float g_att[BW];
__device__ float g_bagz0[NB * FEATP];
__device__ float g_bagz[NB * FEATP];
__device__ float g_ccn[2 * FEATP];
__device__ float g_q[NB * HH];
__device__ float g_k2[2 * HH];
__device__ float g_v2[2 * HH];
__device__ float g_fcx[NB * HH];
__device__ float g_t1[NB * DD];

// ---------------- PTX helpers (generic, sm_80-level) ----------------
__device__ __forceinline__ uint32_t smem_u32(const void* p) {
    uint32_t a;
    asm("{ .reg .u64 t; cvta.to.shared.u64 t, %1; cvt.u32.u64 %0, t; }" : "=r"(a) : "l"(p));
    return a;
}
#define CP_ASYNC16(dst, src) \
    asm volatile("cp.async.cg.shared.global [%0], [%1], 16;" \
                 :: "r"(dst), "l"(src) : "memory")
#define CP_COMMIT() asm volatile("cp.async.commit_group;" ::: "memory")
#define CP_WAIT(n)  asm volatile("cp.async.wait_group %0;" :: "n"(n) : "memory")

__device__ __forceinline__ void ldm_x4(uint32_t& r0, uint32_t& r1, uint32_t& r2, uint32_t& r3,
                                       uint32_t addr) {
    asm volatile("ldmatrix.sync.aligned.m8n8.x4.shared.b16 {%0,%1,%2,%3}, [%4];"
                 : "=r"(r0), "=r"(r1), "=r"(r2), "=r"(r3) : "r"(addr));
}
__device__ __forceinline__ void mma16816(float* c, const uint32_t* a, const uint32_t* b) {
    asm volatile(
        "mma.sync.aligned.m16n8k16.row.col.f32.f16.f16.f32 "
        "{%0,%1,%2,%3}, {%4,%5,%6,%7}, {%8,%9}, {%0,%1,%2,%3};"
        : "+f"(c[0]), "+f"(c[1]), "+f"(c[2]), "+f"(c[3])
        : "r"(a[0]), "r"(a[1]), "r"(a[2]), "r"(a[3]), "r"(b[0]), "r"(b[1]));
}
__device__ __forceinline__ float fast_tanh(float x) {
    float e = __expf(2.0f * x);
    return 1.0f - 2.0f / (e + 1.0f);
}

// ---------------- triu index table (padded to FEATP with 0) ----------------
__global__ void init_off_kernel() {
    int i = blockIdx.x;                      // 0..ROI-1
    if (i == ROI - 1) {                      // padding block
        for (int f = FEAT + threadIdx.x; f < FEATP; f += blockDim.x) g_off[f] = 0;
        return;
    }
    int base = i * (ROI - 1) - i * (i - 1) / 2;
    int cnt = ROI - 1 - i;
    for (int jj = threadIdx.x; jj < cnt; jj += blockDim.x)
        g_off[base + jj] = i * ROI + (i + 1 + jj);
}

// ---------------- init biases into accumulator buffers (post-GEMM ones) ----
__global__ void init_misc_kernel(const float* __restrict__ bq,
                                 const float* __restrict__ bk,
                                 const float* __restrict__ bc1) {
    int idx = blockIdx.x * 256 + threadIdx.x;
    if (idx < NB * HH) { g_q[idx] = bq[idx & (HH - 1)]; return; }
    idx -= NB * HH;
    if (idx < 2 * HH) { g_k2[idx] = bk[idx & (HH - 1)]; return; }
    idx -= 2 * HH;
    if (idx < 2 * HH) { g_v2[idx] = bq[idx & (HH - 1)]; return; }
    idx -= 2 * HH;
    if (idx < NB * DD) { g_t1[idx] = bc1[idx & (DD - 1)]; return; }
}

// ---------------- W1 -> W1T fp16 ([N][K], padded); also inits g_a = b2 ----
__global__ void w1t_kernel(const float* __restrict__ W1, const float* __restrict__ b2) {
    __shared__ float t[32][33];
    int kb = blockIdx.x * 32, nb = blockIdx.y * 32;
    int tx = threadIdx.x, ty = threadIdx.y;
    if (blockIdx.x == 0 && blockIdx.y == 0) {
        int tid = ty * 32 + tx;
        float v = b2[0];
        for (int i = tid; i < BW; i += 256) g_a[i] = v;
    }
#pragma unroll
    for (int i = 0; i < 32; i += 8) {
        int k = kb + ty + i;
        t[ty + i][tx] = (k < FEAT) ? W1[(size_t)k * DD + nb + tx] : 0.f;
    }
    __syncthreads();
#pragma unroll
    for (int i = 0; i < 32; i += 8) {
        float v = t[tx][ty + i];
        g_w1th[(size_t)(nb + ty + i) * FEATP + kb + tx] = __float2half_rn(v);
    }
}

// ---------------- gather -> fp16 (8 features per thread, 16B store) -------
__global__ void gather_kernel(const float* __restrict__ FC) {
    int bw = blockIdx.y;
    int f0 = (blockIdx.x * 256 + threadIdx.x) * 8;
    if (f0 >= FEATP) return;
    const float* src = FC + (size_t)bw * (ROI * ROI);
    int4 oa = *reinterpret_cast<const int4*>(g_off + f0);
    int4 ob = *reinterpret_cast<const int4*>(g_off + f0 + 4);
    __half h[8];
    h[0] = (f0 + 0 < FEAT) ? __float2half_rn(src[oa.x]) : __half(0.f);
    h[1] = (f0 + 1 < FEAT) ? __float2half_rn(src[oa.y]) : __half(0.f);
    h[2] = (f0 + 2 < FEAT) ? __float2half_rn(src[oa.z]) : __half(0.f);
    h[3] = (f0 + 3 < FEAT) ? __float2half_rn(src[oa.w]) : __half(0.f);
    h[4] = (f0 + 4 < FEAT) ? __float2half_rn(src[ob.x]) : __half(0.f);
    h[5] = (f0 + 5 < FEAT) ? __float2half_rn(src[ob.y]) : __half(0.f);
    h[6] = (f0 + 6 < FEAT) ? __float2half_rn(src[ob.z]) : __half(0.f);
    h[7] = (f0 + 7 < FEAT) ? __float2half_rn(src[ob.w]) : __half(0.f);
    *reinterpret_cast<float4*>(g_bag + (size_t)bw * FEATP + f0) =
        *reinterpret_cast<const float4*>(h);
}

// ---------------- HMMA GEMM: S = bag @ W1T^T (fp16), fused tanh/W2 epi ----
// CTA 128x128, 8 warps (4Mx2N), warp tile 32x64. K-stage 64, 3-stage
// pipeline (CP_WAIT(1)), one __syncthreads per stage. rows 144B.
#define LDA       144
#define TILE_B    18432               // 128 rows x 144B
#define STAGE_B   (2 * TILE_B)        // A + B = 36864
#define GEMM_SMEM (3 * STAGE_B)       // 110592

__device__ __forceinline__ void load_stage(uint32_t sdst, int k0, int m0, int n0, int tid) {
    int row = tid >> 1;
    int cb = (tid & 1) * 64;          // byte offset within 128B row half
    uint32_t so = sdst + row * LDA + cb;
    size_t ga = ((size_t)(m0 + row) * FEATP + k0) * 2 + cb;
    size_t gb = ((size_t)(n0 + row) * FEATP + k0) * 2 + cb;
    unsigned long long pa = __cvta_generic_to_global((const char*)g_bag + ga);
    unsigned long long pb = __cvta_generic_to_global((const char*)g_w1th + gb);
    CP_ASYNC16(so,      pa);      CP_ASYNC16(so + 16, pa + 16);
    CP_ASYNC16(so + 32, pa + 32); CP_ASYNC16(so + 48, pa + 48);
    so += TILE_B;
    CP_ASYNC16(so,      pb);      CP_ASYNC16(so + 16, pb + 16);
    CP_ASYNC16(so + 32, pb + 32); CP_ASYNC16(so + 48, pb + 48);
}

__global__ __launch_bounds__(256, 2) void gemm_mma_kernel(const float* __restrict__ b1,
                                                          const float* __restrict__ W2) {
    extern __shared__ char sm[];
    const uint32_t sbase = smem_u32(sm);
    const int tid = threadIdx.x, lane = tid & 31, wid = tid >> 5;
    const int wm = wid & 3, wn = wid >> 2;        // 4 M-warps x 2 N-warps
    const int n0 = blockIdx.x * 128, m0 = blockIdx.y * 128;

    float acc[2][8][4];
#pragma unroll
    for (int mt = 0; mt < 2; mt++)
#pragma unroll
        for (int nt = 0; nt < 8; nt++)
#pragma unroll
            for (int c = 0; c < 4; c++) acc[mt][nt][c] = 0.f;

    load_stage(sbase, 0, m0, n0, tid);             CP_COMMIT();
    load_stage(sbase + STAGE_B, 64, m0, n0, tid);  CP_COMMIT();

    const uint32_t aRowOfs = (uint32_t)(wm * 32 + ((lane >> 3) & 1) * 8 + (lane & 7)) * LDA
                           + (uint32_t)(lane >> 4) * 16;
    const uint32_t bRowOfs = (uint32_t)(wn * 64 + (lane >> 4) * 8 + (lane & 7)) * LDA
                           + (uint32_t)((lane >> 3) & 1) * 16;

    int slot = 0;
    for (int i = 0; i < NSTG64; i++) {
        if (i + 1 < NSTG64) { CP_WAIT(1); } else { CP_WAIT(0); }
        __syncthreads();
        if (i + 2 < NSTG64) {
            int ns = slot + 2; if (ns >= 3) ns -= 3;
            load_stage(sbase + (uint32_t)ns * STAGE_B, (i + 2) * 64, m0, n0, tid);
            CP_COMMIT();
        }
        const uint32_t st = sbase + (uint32_t)slot * STAGE_B;
#pragma unroll
        for (int kk = 0; kk < 4; kk++) {
            uint32_t aH[2][4], bb[8][2];
#pragma unroll
            for (int mt = 0; mt < 2; mt++)
                ldm_x4(aH[mt][0], aH[mt][1], aH[mt][2], aH[mt][3],
                       st + aRowOfs + (uint32_t)mt * 16 * LDA + kk * 32);
#pragma unroll
            for (int p = 0; p < 4; p++)
                ldm_x4(bb[2 * p][0], bb[2 * p][1], bb[2 * p + 1][0], bb[2 * p + 1][1],
                       st + TILE_B + bRowOfs + (uint32_t)p * 16 * LDA + kk * 32);
#pragma unroll
            for (int mt = 0; mt < 2; mt++)
#pragma unroll
                for (int nt = 0; nt < 8; nt++) mma16816(acc[mt][nt], aH[mt], bb[nt]);
        }
        if (++slot == 3) slot = 0;
    }

    // epilogue: per-row sum over n of tanh(S + b1)*W2, reduce, atomicAdd
    const int g = lane >> 2, t4 = lane & 3;
#pragma unroll
    for (int mt = 0; mt < 2; mt++) {
        float sA = 0.f, sB = 0.f;
#pragma unroll
        for (int nt = 0; nt < 8; nt++) {
            int c0 = n0 + wn * 64 + nt * 8 + 2 * t4;
            float b1a = b1[c0], b1b = b1[c0 + 1];
            float w2a = W2[c0], w2b = W2[c0 + 1];
            sA += fast_tanh(acc[mt][nt][0] + b1a) * w2a + fast_tanh(acc[mt][nt][1] + b1b) * w2b;
            sB += fast_tanh(acc[mt][nt][2] + b1a) * w2a + fast_tanh(acc[mt][nt][3] + b1b) * w2b;
        }
        sA += __shfl_xor_sync(0xFFFFFFFF, sA, 1);
        sA += __shfl_xor_sync(0xFFFFFFFF, sA, 2);
        sB += __shfl_xor_sync(0xFFFFFFFF, sB, 1);
        sB += __shfl_xor_sync(0xFFFFFFFF, sB, 2);
        if (t4 == 0) {
            int r = m0 + wm * 32 + mt * 16 + g;
            atomicAdd(&g_a[r], sA);
            atomicAdd(&g_a[r + 8], sB);
        }
    }
}

// ---------------- softmax over W per batch ----------------
__global__ void softmax_kernel() {
    int b = blockIdx.x, t = threadIdx.x;  // 128 threads
    __shared__ float sv[128];
    float v = g_a[b * NW + t];
    sv[t] = v; __syncthreads();
    for (int s = 64; s > 0; s >>= 1) { if (t < s) sv[t] = fmaxf(sv[t], sv[t + s]); __syncthreads(); }
    float m = sv[0]; __syncthreads();
    float e = expf(v - m);
    sv[t] = e; __syncthreads();
    for (int s = 64; s > 0; s >>= 1) { if (t < s) sv[t] += sv[t + s]; __syncthreads(); }
    g_att[b * NW + t] = e / sv[0];
}

// ---------------- attention pool (2 features per thread, half2 loads) -----
__global__ void pool_kernel() {
    int b = blockIdx.y;
    int f0 = (blockIdx.x * 256 + threadIdx.x) * 2;
    __shared__ float sat[NW];
    if (threadIdx.x < NW) sat[threadIdx.x] = g_att[b * NW + threadIdx.x];
    __syncthreads();
    if (f0 >= FEAT) return;
    float acc0 = 0.f, acc1 = 0.f;
    const __half2* bh = reinterpret_cast<const __half2*>(g_bag + (size_t)b * NW * FEATP + f0);
#pragma unroll 4
    for (int w = 0; w < NW; w++) {
        float2 v = __half22float2(bh[(size_t)w * (FEATP / 2)]);
        float a = sat[w];
        acc0 += a * v.x;
        acc1 += a * v.y;
    }
    g_bagz0[b * FEATP + f0] = acc0;
    if (f0 + 1 < FEAT) g_bagz0[b * FEATP + f0 + 1] = acc1;
}

// ---------------- batchnorms ----------------
__global__ void bn_kernel(const float* __restrict__ cc,
                          const float* __restrict__ bn_g, const float* __restrict__ bn_b,
                          const float* __restrict__ bn2_g, const float* __restrict__ bn2_b) {
    int f = blockIdx.x * 256 + threadIdx.x;
    if (f >= FEAT) return;
    float mu = 0.f;
    for (int b = 0; b < NB; b++) mu += g_bagz0[b * FEATP + f];
    mu *= (1.f / NB);
    float var = 0.f;
    for (int b = 0; b < NB; b++) { float d = g_bagz0[b * FEATP + f] - mu; var += d * d; }
    var *= (1.f / NB);
    float inv = rsqrtf(var + 1e-5f);
    float g = bn_g[f], bt = bn_b[f];
    for (int b = 0; b < NB; b++)
        g_bagz[b * FEATP + f] = (g_bagz0[b * FEATP + f] - mu) * inv * g + bt;
    float c0 = cc[f], c1 = cc[FEAT + f];
    float mu2 = 0.5f * (c0 + c1);
    float d0 = c0 - mu2, d1 = c1 - mu2;
    float inv2 = rsqrtf(0.5f * (d0 * d0 + d1 * d1) + 1e-5f);
    float g2 = bn2_g[f], b2v = bn2_b[f];
    g_ccn[f] = d0 * inv2 * g2 + b2v;
    g_ccn[FEATP + f] = d1 * inv2 * g2 + b2v;
}

// ---------------- skinny GEMM: C[M,N] += A[M,K] @ B[K,N], split-K atomics ----
template <int M>
__global__ __launch_bounds__(256) void skinny_kernel(int selA, int lda,
                                                     const float* __restrict__ B, int ldb,
                                                     int selC, int K, int N) {
    const float* A = (selA == 0) ? g_bagz : (selA == 1) ? g_ccn : g_fcx;
    float* C = (selC == 0) ? g_q : (selC == 1) ? g_k2 : (selC == 2) ? g_v2 : g_t1;
    __shared__ float sA[M][33];
    int tid = threadIdx.x;
    int col = blockIdx.x * 256 + tid;
    int nsplit = gridDim.y;
    int len = (K + nsplit - 1) / nsplit;
    int k0 = blockIdx.y * len;
    int kend = min(K, k0 + len);
    float acc[M];
#pragma unroll
    for (int m = 0; m < M; m++) acc[m] = 0.f;
    for (int kb = k0; kb < kend; kb += 32) {
        int kmax = min(32, kend - kb);
        for (int idx = tid; idx < M * 32; idx += 256) {
            int m = idx >> 5, kk = idx & 31;
            sA[m][kk] = (kk < kmax) ? A[(size_t)m * lda + kb + kk] : 0.f;
        }
        __syncthreads();
        if (col < N) {
            const float* Bp = B + (size_t)kb * ldb + col;
            int kk = 0;
            for (; kk + 4 <= kmax; kk += 4) {
                float bv0 = Bp[0];
                float bv1 = Bp[(size_t)ldb];
                float bv2 = Bp[2 * (size_t)ldb];
                float bv3 = Bp[3 * (size_t)ldb];
                Bp += 4 * (size_t)ldb;
#pragma unroll
                for (int m = 0; m < M; m++) acc[m] += sA[m][kk] * bv0;
#pragma unroll
                for (int m = 0; m < M; m++) acc[m] += sA[m][kk + 1] * bv1;
#pragma unroll
                for (int m = 0; m < M; m++) acc[m] += sA[m][kk + 2] * bv2;
#pragma unroll
                for (int m = 0; m < M; m++) acc[m] += sA[m][kk + 3] * bv3;
            }
            for (; kk < kmax; kk++) {
                float bv = Bp[0]; Bp += (size_t)ldb;
#pragma unroll
                for (int m = 0; m < M; m++) acc[m] += sA[m][kk] * bv;
            }
        }
        __syncthreads();
    }
    if (col < N) {
#pragma unroll
        for (int m = 0; m < M; m++) atomicAdd(&C[(size_t)m * N + col], acc[m]);
    }
}

// ---------------- merged k/v skinny: k2 += ccn@Wk, v2 += ccn@Wq ----------------
__global__ __launch_bounds__(256) void kv_kernel(const float* __restrict__ Wk,
                                                 const float* __restrict__ Wq) {
    __shared__ float sA[2][33];
    int tid = threadIdx.x;
    int col = blockIdx.x * 256 + tid;   // < HH
    int nsplit = gridDim.y;
    int len = (FEAT + nsplit - 1) / nsplit;
    int k0 = blockIdx.y * len;
    int kend = min(FEAT, k0 + len);
    float ak0 = 0.f, ak1 = 0.f, av0 = 0.f, av1 = 0.f;
    for (int kb = k0; kb < kend; kb += 32) {
        int kmax = min(32, kend - kb);
        if (tid < 64) {
            int m = tid >> 5, kk = tid & 31;
            sA[m][kk] = (kk < kmax) ? g_ccn[(size_t)m * FEATP + kb + kk] : 0.f;
        }
        __syncthreads();
        const float* Kp = Wk + (size_t)kb * HH + col;
        const float* Qp = Wq + (size_t)kb * HH + col;
        int kk = 0;
        for (; kk + 2 <= kmax; kk += 2) {
            float k0v = Kp[0], k1v = Kp[HH];
            float q0v = Qp[0], q1v = Qp[HH];
            Kp += 2 * HH; Qp += 2 * HH;
            ak0 += sA[0][kk] * k0v; ak1 += sA[1][kk] * k0v;
            av0 += sA[0][kk] * q0v; av1 += sA[1][kk] * q0v;
            ak0 += sA[0][kk + 1] * k1v; ak1 += sA[1][kk + 1] * k1v;
            av0 += sA[0][kk + 1] * q1v; av1 += sA[1][kk + 1] * q1v;
        }
        for (; kk < kmax; kk++) {
            float kv = Kp[0], qv = Qp[0]; Kp += HH; Qp += HH;
            ak0 += sA[0][kk] * kv; ak1 += sA[1][kk] * kv;
            av0 += sA[0][kk] * qv; av1 += sA[1][kk] * qv;
        }
        __syncthreads();
    }
    atomicAdd(&g_k2[col], ak0);
    atomicAdd(&g_k2[HH + col], ak1);
    atomicAdd(&g_v2[col], av0);
    atomicAdd(&g_v2[HH + col], av1);
}

// ---------------- cross attention ----------------
__global__ void cross_kernel() {
    __shared__ float sQK[64][2];
    __shared__ float sac[64][2];
    int t = threadIdx.x;  // 256
    if (t < 128) {
        int b = t >> 1, r = t & 1;
        const float* qp = g_q + b * HH;
        const float* kp = g_k2 + r * HH;
        float acc = 0.f;
        for (int d = 0; d < HH; d++) acc += qp[d] * kp[d];
        sQK[b][r] = acc * (1.0f / 32.0f);
    }
    __syncthreads();
    if (t < 64) {
        float x0 = sQK[t][0], x1 = sQK[t][1];
        float m = fmaxf(x0, x1);
        float e0 = expf(x0 - m), e1 = expf(x1 - m);
        float inv = 1.f / (e0 + e1);
        sac[t][0] = e0 * inv; sac[t][1] = e1 * inv;
    }
    __syncthreads();
    for (int idx = t; idx < NB * HH; idx += 256) {
        int b = idx >> 10, d = idx & 1023;
        g_fcx[idx] = sac[b][0] * g_v2[d] + sac[b][1] * g_v2[HH + d];
    }
}

// ---------------- classifier head ----------------
__global__ void final_kernel(const float* __restrict__ Wc2, const float* __restrict__ bc2,
                             float* __restrict__ out, int out_size) {
    int b = blockIdx.x, t = threadIdx.x;
    float acc = 0.f;
    for (int d = t; d < DD; d += 256) acc += fmaxf(g_t1[b * DD + d], 0.f) * Wc2[d];
    __shared__ float red[256];
    red[t] = acc; __syncthreads();
    for (int s = 128; s > 0; s >>= 1) { if (t < s) red[t] += red[t + s]; __syncthreads(); }
    if (t == 0) {
        float y = 1.f / (1.f + expf(-(red[0] + bc2[0])));
        out[b] = y;
        if (64 + b < out_size) out[64 + b] = (y >= 0.5f) ? 1.f : 0.f;
    }
}

// ---------------- launch ----------------
extern "C" void kernel_launch(void* const* d_in, const int* in_sizes, int n_in,
                              void* d_out, int out_size) {
    const float* FC    = (const float*)d_in[0];
    const float* cc    = (const float*)d_in[1];
    const float* W1    = (const float*)d_in[2];
    const float* b1    = (const float*)d_in[3];
    const float* W2    = (const float*)d_in[4];
    const float* b2    = (const float*)d_in[5];
    const float* bn_g  = (const float*)d_in[6];
    const float* bn_b  = (const float*)d_in[7];
    const float* bn2_g = (const float*)d_in[8];
    const float* bn2_b = (const float*)d_in[9];
    const float* Wq    = (const float*)d_in[10];
    const float* bq    = (const float*)d_in[11];
    const float* Wk    = (const float*)d_in[12];
    const float* bk    = (const float*)d_in[13];
    const float* Wc1   = (const float*)d_in[14];
    const float* bc1   = (const float*)d_in[15];
    const float* Wc2   = (const float*)d_in[16];
    const float* bc2   = (const float*)d_in[17];
    float* out = (float*)d_out;

    cudaFuncSetAttribute(gemm_mma_kernel, cudaFuncAttributeMaxDynamicSharedMemorySize, GEMM_SMEM);

    init_off_kernel<<<ROI, 128>>>();                                        // 1
    init_misc_kernel<<<(NB * HH + 4 * HH + NB * DD + 255) / 256, 256>>>(bq, bk, bc1);  // 2
    w1t_kernel<<<dim3(FEATP / 32, DD / 32), dim3(32, 8)>>>(W1, b2);         // 3
    gather_kernel<<<dim3(4, BW), 256>>>(FC);                                // 4 (ncu slot)
    gemm_mma_kernel<<<dim3(8, 64), 256, GEMM_SMEM>>>(b1, W2);               // 5
    softmax_kernel<<<NB, 128>>>();
    pool_kernel<<<dim3((FEAT / 2 + 255) / 256, NB), 256>>>();
    bn_kernel<<<(FEAT + 255) / 256, 256>>>(cc, bn_g, bn_b, bn2_g, bn2_b);
    skinny_kernel<64><<<dim3(4, 104), 256>>>(0, FEATP, Wq, HH, 0, FEAT, HH);
    kv_kernel<<<dim3(4, 16), 256>>>(Wk, Wq);
    cross_kernel<<<1, 256>>>();
    skinny_kernel<64><<<dim3(4, 16), 256>>>(2, HH, Wc1, DD, 3, HH, DD);
    skinny_kernel<64><<<dim3(4, 104), 256>>>(0, FEATP, Wc1 + (size_t)HH * DD, DD, 3, FEAT, DD);
    final_kernel<<<NB, 256>>>(Wc2, bc2, out, out_size);
}

// round 13
// speedup vs baseline: 1.2970x; 1.0398x over previous
#include <cuda_runtime.h>
#include <cuda_fp16.h>
#include <math.h>
#include <stdint.h>

#define ROI   116
#define FEAT  6670      // ROI*(ROI-1)/2
#define FEATP 6720      // padded to multiple of 64
#define NB    64        // batch
#define NW    128       // bags per batch
#define BW    8192      // NB*NW
#define DD    1024
#define HH    1024
#define NSTG64 (FEATP / 64)  // 105 K-stages of 64

// ---------------- scratch (device globals; no allocation) ----------------
__device__ __align__(16) __half g_bag[(size_t)BW * FEATP];   // 110 MB
__device__ __align__(16) __half g_w1th[(size_t)DD * FEATP];  // 13.8 MB  [N][K]
__device__ __align__(16) int g_off[FEATP];
__device__ float g_a[BW];
__device__ float g_att[BW];
__device__ float g_bagz0[NB * FEATP];
__device__ float g_bagz[NB * FEATP];
__device__ float g_ccn[2 * FEATP];
__device__ float g_q[NB * HH];
__device__ float g_k2[2 * HH];
__device__ float g_v2[2 * HH];
__device__ float g_fcx[NB * HH];
__device__ float g_t1[NB * DD];

// ---------------- PTX helpers (generic, sm_80-level) ----------------
__device__ __forceinline__ uint32_t smem_u32(const void* p) {
    uint32_t a;
    asm("{ .reg .u64 t; cvta.to.shared.u64 t, %1; cvt.u32.u64 %0, t; }" : "=r"(a) : "l"(p));
    return a;
}
#define CP_ASYNC16(dst, src) \
    asm volatile("cp.async.cg.shared.global [%0], [%1], 16;" \
                 :: "r"(dst), "l"(src) : "memory")
#define CP_COMMIT() asm volatile("cp.async.commit_group;" ::: "memory")
#define CP_WAIT(n)  asm volatile("cp.async.wait_group %0;" :: "n"(n) : "memory")

__device__ __forceinline__ void ldm_x4(uint32_t& r0, uint32_t& r1, uint32_t& r2, uint32_t& r3,
                                       uint32_t addr) {
    asm volatile("ldmatrix.sync.aligned.m8n8.x4.shared.b16 {%0,%1,%2,%3}, [%4];"
                 : "=r"(r0), "=r"(r1), "=r"(r2), "=r"(r3) : "r"(addr));
}
__device__ __forceinline__ void mma16816(float* c, const uint32_t* a, const uint32_t* b) {
    asm volatile(
        "mma.sync.aligned.m16n8k16.row.col.f32.f16.f16.f32 "
        "{%0,%1,%2,%3}, {%4,%5,%6,%7}, {%8,%9}, {%0,%1,%2,%3};"
        : "+f"(c[0]), "+f"(c[1]), "+f"(c[2]), "+f"(c[3])
        : "r"(a[0]), "r"(a[1]), "r"(a[2]), "r"(a[3]), "r"(b[0]), "r"(b[1]));
}
__device__ __forceinline__ float fast_tanh(float x) {
    float e = __expf(2.0f * x);
    return 1.0f - 2.0f / (e + 1.0f);
}

// ---------------- triu index table (padded to FEATP with 0) ----------------
__global__ void init_off_kernel() {
    int i = blockIdx.x;                      // 0..ROI-1
    if (i == ROI - 1) {                      // padding block
        for (int f = FEAT + threadIdx.x; f < FEATP; f += blockDim.x) g_off[f] = 0;
        return;
    }
    int base = i * (ROI - 1) - i * (i - 1) / 2;
    int cnt = ROI - 1 - i;
    for (int jj = threadIdx.x; jj < cnt; jj += blockDim.x)
        g_off[base + jj] = i * ROI + (i + 1 + jj);
}

// ---------------- init biases into accumulator buffers (post-GEMM ones) ----
__global__ void init_misc_kernel(const float* __restrict__ bq,
                                 const float* __restrict__ bk,
                                 const float* __restrict__ bc1) {
    int idx = blockIdx.x * 256 + threadIdx.x;
    if (idx < NB * HH) { g_q[idx] = bq[idx & (HH - 1)]; return; }
    idx -= NB * HH;
    if (idx < 2 * HH) { g_k2[idx] = bk[idx & (HH - 1)]; return; }
    idx -= 2 * HH;
    if (idx < 2 * HH) { g_v2[idx] = bq[idx & (HH - 1)]; return; }
    idx -= 2 * HH;
    if (idx < NB * DD) { g_t1[idx] = bc1[idx & (DD - 1)]; return; }
}

// ---------------- W1 -> W1T fp16 ([N][K], padded); also inits g_a = b2 ----
__global__ void w1t_kernel(const float* __restrict__ W1, const float* __restrict__ b2) {
    __shared__ float t[32][33];
    int kb = blockIdx.x * 32, nb = blockIdx.y * 32;
    int tx = threadIdx.x, ty = threadIdx.y;
    if (blockIdx.x == 0 && blockIdx.y == 0) {
        int tid = ty * 32 + tx;
        float v = b2[0];
        for (int i = tid; i < BW; i += 256) g_a[i] = v;
    }
#pragma unroll
    for (int i = 0; i < 32; i += 8) {
        int k = kb + ty + i;
        t[ty + i][tx] = (k < FEAT) ? W1[(size_t)k * DD + nb + tx] : 0.f;
    }
    __syncthreads();
#pragma unroll
    for (int i = 0; i < 32; i += 8) {
        float v = t[tx][ty + i];
        g_w1th[(size_t)(nb + ty + i) * FEATP + kb + tx] = __float2half_rn(v);
    }
}

// ---------------- gather -> fp16 (8 features per thread, 16B store) -------
__global__ void gather_kernel(const float* __restrict__ FC) {
    int bw = blockIdx.y;
    int f0 = (blockIdx.x * 256 + threadIdx.x) * 8;
    if (f0 >= FEATP) return;
    const float* src = FC + (size_t)bw * (ROI * ROI);
    int4 oa = *reinterpret_cast<const int4*>(g_off + f0);
    int4 ob = *reinterpret_cast<const int4*>(g_off + f0 + 4);
    __half h[8];
    h[0] = (f0 + 0 < FEAT) ? __float2half_rn(src[oa.x]) : __half(0.f);
    h[1] = (f0 + 1 < FEAT) ? __float2half_rn(src[oa.y]) : __half(0.f);
    h[2] = (f0 + 2 < FEAT) ? __float2half_rn(src[oa.z]) : __half(0.f);
    h[3] = (f0 + 3 < FEAT) ? __float2half_rn(src[oa.w]) : __half(0.f);
    h[4] = (f0 + 4 < FEAT) ? __float2half_rn(src[ob.x]) : __half(0.f);
    h[5] = (f0 + 5 < FEAT) ? __float2half_rn(src[ob.y]) : __half(0.f);
    h[6] = (f0 + 6 < FEAT) ? __float2half_rn(src[ob.z]) : __half(0.f);
    h[7] = (f0 + 7 < FEAT) ? __float2half_rn(src[ob.w]) : __half(0.f);
    *reinterpret_cast<float4*>(g_bag + (size_t)bw * FEATP + f0) =
        *reinterpret_cast<const float4*>(h);
}

// ---------------- HMMA GEMM: S = bag @ W1T^T (fp16), fused tanh/W2 epi ----
// CTA 128x128, 8 warps (4Mx2N), warp tile 32x64. K-stage 64, 3-stage
// pipeline (CP_WAIT(1)), one __syncthreads per stage. rows 144B.
#define LDA       144
#define TILE_B    18432               // 128 rows x 144B
#define STAGE_B   (2 * TILE_B)        // A + B = 36864
#define GEMM_SMEM (3 * STAGE_B)       // 110592

__device__ __forceinline__ void load_stage(uint32_t sdst, int k0, int m0, int n0, int tid) {
    int row = tid >> 1;
    int cb = (tid & 1) * 64;          // byte offset within 128B row half
    uint32_t so = sdst + row * LDA + cb;
    size_t ga = ((size_t)(m0 + row) * FEATP + k0) * 2 + cb;
    size_t gb = ((size_t)(n0 + row) * FEATP + k0) * 2 + cb;
    unsigned long long pa = __cvta_generic_to_global((const char*)g_bag + ga);
    unsigned long long pb = __cvta_generic_to_global((const char*)g_w1th + gb);
    CP_ASYNC16(so,      pa);      CP_ASYNC16(so + 16, pa + 16);
    CP_ASYNC16(so + 32, pa + 32); CP_ASYNC16(so + 48, pa + 48);
    so += TILE_B;
    CP_ASYNC16(so,      pb);      CP_ASYNC16(so + 16, pb + 16);
    CP_ASYNC16(so + 32, pb + 32); CP_ASYNC16(so + 48, pb + 48);
}

__global__ __launch_bounds__(256, 2) void gemm_mma_kernel(const float* __restrict__ b1,
                                                          const float* __restrict__ W2) {
    extern __shared__ char sm[];
    const uint32_t sbase = smem_u32(sm);
    const int tid = threadIdx.x, lane = tid & 31, wid = tid >> 5;
    const int wm = wid & 3, wn = wid >> 2;        // 4 M-warps x 2 N-warps
    const int n0 = blockIdx.x * 128, m0 = blockIdx.y * 128;

    float acc[2][8][4];
#pragma unroll
    for (int mt = 0; mt < 2; mt++)
#pragma unroll
        for (int nt = 0; nt < 8; nt++)
#pragma unroll
            for (int c = 0; c < 4; c++) acc[mt][nt][c] = 0.f;

    load_stage(sbase, 0, m0, n0, tid);             CP_COMMIT();
    load_stage(sbase + STAGE_B, 64, m0, n0, tid);  CP_COMMIT();

    const uint32_t aRowOfs = (uint32_t)(wm * 32 + ((lane >> 3) & 1) * 8 + (lane & 7)) * LDA
                           + (uint32_t)(lane >> 4) * 16;
    const uint32_t bRowOfs = (uint32_t)(wn * 64 + (lane >> 4) * 8 + (lane & 7)) * LDA
                           + (uint32_t)((lane >> 3) & 1) * 16;

    int slot = 0;
    for (int i = 0; i < NSTG64; i++) {
        if (i + 1 < NSTG64) { CP_WAIT(1); } else { CP_WAIT(0); }
        __syncthreads();
        if (i + 2 < NSTG64) {
            int ns = slot + 2; if (ns >= 3) ns -= 3;
            load_stage(sbase + (uint32_t)ns * STAGE_B, (i + 2) * 64, m0, n0, tid);
            CP_COMMIT();
        }
        const uint32_t st = sbase + (uint32_t)slot * STAGE_B;
#pragma unroll
        for (int kk = 0; kk < 4; kk++) {
            uint32_t aH[2][4], bb[8][2];
#pragma unroll
            for (int mt = 0; mt < 2; mt++)
                ldm_x4(aH[mt][0], aH[mt][1], aH[mt][2], aH[mt][3],
                       st + aRowOfs + (uint32_t)mt * 16 * LDA + kk * 32);
#pragma unroll
            for (int p = 0; p < 4; p++)
                ldm_x4(bb[2 * p][0], bb[2 * p][1], bb[2 * p + 1][0], bb[2 * p + 1][1],
                       st + TILE_B + bRowOfs + (uint32_t)p * 16 * LDA + kk * 32);
#pragma unroll
            for (int mt = 0; mt < 2; mt++)
#pragma unroll
                for (int nt = 0; nt < 8; nt++) mma16816(acc[mt][nt], aH[mt], bb[nt]);
        }
        if (++slot == 3) slot = 0;
    }

    // epilogue: per-row sum over n of tanh(S + b1)*W2, reduce, atomicAdd
    const int g = lane >> 2, t4 = lane & 3;
#pragma unroll
    for (int mt = 0; mt < 2; mt++) {
        float sA = 0.f, sB = 0.f;
#pragma unroll
        for (int nt = 0; nt < 8; nt++) {
            int c0 = n0 + wn * 64 + nt * 8 + 2 * t4;
            float b1a = b1[c0], b1b = b1[c0 + 1];
            float w2a = W2[c0], w2b = W2[c0 + 1];
            sA += fast_tanh(acc[mt][nt][0] + b1a) * w2a + fast_tanh(acc[mt][nt][1] + b1b) * w2b;
            sB += fast_tanh(acc[mt][nt][2] + b1a) * w2a + fast_tanh(acc[mt][nt][3] + b1b) * w2b;
        }
        sA += __shfl_xor_sync(0xFFFFFFFF, sA, 1);
        sA += __shfl_xor_sync(0xFFFFFFFF, sA, 2);
        sB += __shfl_xor_sync(0xFFFFFFFF, sB, 1);
        sB += __shfl_xor_sync(0xFFFFFFFF, sB, 2);
        if (t4 == 0) {
            int r = m0 + wm * 32 + mt * 16 + g;
            atomicAdd(&g_a[r], sA);
            atomicAdd(&g_a[r + 8], sB);
        }
    }
}

// ---------------- softmax over W per batch ----------------
__global__ void softmax_kernel() {
    int b = blockIdx.x, t = threadIdx.x;  // 128 threads
    __shared__ float sv[128];
    float v = g_a[b * NW + t];
    sv[t] = v; __syncthreads();
    for (int s = 64; s > 0; s >>= 1) { if (t < s) sv[t] = fmaxf(sv[t], sv[t + s]); __syncthreads(); }
    float m = sv[0]; __syncthreads();
    float e = expf(v - m);
    sv[t] = e; __syncthreads();
    for (int s = 64; s > 0; s >>= 1) { if (t < s) sv[t] += sv[t + s]; __syncthreads(); }
    g_att[b * NW + t] = e / sv[0];
}

// ---------------- attention pool (4 features per thread, 8B loads) --------
__global__ void pool_kernel() {
    int b = blockIdx.y;
    int f0 = (blockIdx.x * 256 + threadIdx.x) * 4;
    __shared__ float sat[NW];
    if (threadIdx.x < NW) sat[threadIdx.x] = g_att[b * NW + threadIdx.x];
    __syncthreads();
    if (f0 >= FEAT) return;
    float a0 = 0.f, a1 = 0.f, a2 = 0.f, a3 = 0.f;
    const __half2* bh = reinterpret_cast<const __half2*>(g_bag + (size_t)b * NW * FEATP + f0);
#pragma unroll 4
    for (int w = 0; w < NW; w++) {
        const __half2* p = bh + (size_t)w * (FEATP / 2);
        float2 v01 = __half22float2(p[0]);
        float2 v23 = __half22float2(p[1]);
        float a = sat[w];
        a0 += a * v01.x; a1 += a * v01.y;
        a2 += a * v23.x; a3 += a * v23.y;
    }
    float* dst = g_bagz0 + (size_t)b * FEATP + f0;
    dst[0] = a0;
    if (f0 + 1 < FEAT) dst[1] = a1;
    if (f0 + 2 < FEAT) dst[2] = a2;
    if (f0 + 3 < FEAT) dst[3] = a3;
}

// ---------------- batchnorms ----------------
__global__ void bn_kernel(const float* __restrict__ cc,
                          const float* __restrict__ bn_g, const float* __restrict__ bn_b,
                          const float* __restrict__ bn2_g, const float* __restrict__ bn2_b) {
    int f = blockIdx.x * 256 + threadIdx.x;
    if (f >= FEAT) return;
    float mu = 0.f;
    for (int b = 0; b < NB; b++) mu += g_bagz0[b * FEATP + f];
    mu *= (1.f / NB);
    float var = 0.f;
    for (int b = 0; b < NB; b++) { float d = g_bagz0[b * FEATP + f] - mu; var += d * d; }
    var *= (1.f / NB);
    float inv = rsqrtf(var + 1e-5f);
    float g = bn_g[f], bt = bn_b[f];
    for (int b = 0; b < NB; b++)
        g_bagz[b * FEATP + f] = (g_bagz0[b * FEATP + f] - mu) * inv * g + bt;
    float c0 = cc[f], c1 = cc[FEAT + f];
    float mu2 = 0.5f * (c0 + c1);
    float d0 = c0 - mu2, d1 = c1 - mu2;
    float inv2 = rsqrtf(0.5f * (d0 * d0 + d1 * d1) + 1e-5f);
    float g2 = bn2_g[f], b2v = bn2_b[f];
    g_ccn[f] = d0 * inv2 * g2 + b2v;
    g_ccn[FEATP + f] = d1 * inv2 * g2 + b2v;
}

// ---------------- skinny GEMM: C[M,N] += A[M,K] @ B[K,N], split-K atomics ----
template <int M>
__global__ __launch_bounds__(256) void skinny_kernel(int selA, int lda,
                                                     const float* __restrict__ B, int ldb,
                                                     int selC, int K, int N) {
    const float* A = (selA == 0) ? g_bagz : (selA == 1) ? g_ccn : g_fcx;
    float* C = (selC == 0) ? g_q : (selC == 1) ? g_k2 : (selC == 2) ? g_v2 : g_t1;
    __shared__ float sA[M][33];
    int tid = threadIdx.x;
    int col = blockIdx.x * 256 + tid;
    int nsplit = gridDim.y;
    int len = (K + nsplit - 1) / nsplit;
    int k0 = blockIdx.y * len;
    int kend = min(K, k0 + len);
    float acc[M];
#pragma unroll
    for (int m = 0; m < M; m++) acc[m] = 0.f;
    for (int kb = k0; kb < kend; kb += 32) {
        int kmax = min(32, kend - kb);
        for (int idx = tid; idx < M * 32; idx += 256) {
            int m = idx >> 5, kk = idx & 31;
            sA[m][kk] = (kk < kmax) ? A[(size_t)m * lda + kb + kk] : 0.f;
        }
        __syncthreads();
        if (col < N) {
            const float* Bp = B + (size_t)kb * ldb + col;
            int kk = 0;
            for (; kk + 4 <= kmax; kk += 4) {
                float bv0 = Bp[0];
                float bv1 = Bp[(size_t)ldb];
                float bv2 = Bp[2 * (size_t)ldb];
                float bv3 = Bp[3 * (size_t)ldb];
                Bp += 4 * (size_t)ldb;
#pragma unroll
                for (int m = 0; m < M; m++) acc[m] += sA[m][kk] * bv0;
#pragma unroll
                for (int m = 0; m < M; m++) acc[m] += sA[m][kk + 1] * bv1;
#pragma unroll
                for (int m = 0; m < M; m++) acc[m] += sA[m][kk + 2] * bv2;
#pragma unroll
                for (int m = 0; m < M; m++) acc[m] += sA[m][kk + 3] * bv3;
            }
            for (; kk < kmax; kk++) {
                float bv = Bp[0]; Bp += (size_t)ldb;
#pragma unroll
                for (int m = 0; m < M; m++) acc[m] += sA[m][kk] * bv;
            }
        }
        __syncthreads();
    }
    if (col < N) {
#pragma unroll
        for (int m = 0; m < M; m++) atomicAdd(&C[(size_t)m * N + col], acc[m]);
    }
}

// ---------------- merged k/v skinny: k2 += ccn@Wk, v2 += ccn@Wq ----------------
__global__ __launch_bounds__(256) void kv_kernel(const float* __restrict__ Wk,
                                                 const float* __restrict__ Wq) {
    __shared__ float sA[2][33];
    int tid = threadIdx.x;
    int col = blockIdx.x * 256 + tid;   // < HH
    int nsplit = gridDim.y;
    int len = (FEAT + nsplit - 1) / nsplit;
    int k0 = blockIdx.y * len;
    int kend = min(FEAT, k0 + len);
    float ak0 = 0.f, ak1 = 0.f, av0 = 0.f, av1 = 0.f;
    for (int kb = k0; kb < kend; kb += 32) {
        int kmax = min(32, kend - kb);
        if (tid < 64) {
            int m = tid >> 5, kk = tid & 31;
            sA[m][kk] = (kk < kmax) ? g_ccn[(size_t)m * FEATP + kb + kk] : 0.f;
        }
        __syncthreads();
        const float* Kp = Wk + (size_t)kb * HH + col;
        const float* Qp = Wq + (size_t)kb * HH + col;
        int kk = 0;
        for (; kk + 2 <= kmax; kk += 2) {
            float k0v = Kp[0], k1v = Kp[HH];
            float q0v = Qp[0], q1v = Qp[HH];
            Kp += 2 * HH; Qp += 2 * HH;
            ak0 += sA[0][kk] * k0v; ak1 += sA[1][kk] * k0v;
            av0 += sA[0][kk] * q0v; av1 += sA[1][kk] * q0v;
            ak0 += sA[0][kk + 1] * k1v; ak1 += sA[1][kk + 1] * k1v;
            av0 += sA[0][kk + 1] * q1v; av1 += sA[1][kk + 1] * q1v;
        }
        for (; kk < kmax; kk++) {
            float kv = Kp[0], qv = Qp[0]; Kp += HH; Qp += HH;
            ak0 += sA[0][kk] * kv; ak1 += sA[1][kk] * kv;
            av0 += sA[0][kk] * qv; av1 += sA[1][kk] * qv;
        }
        __syncthreads();
    }
    atomicAdd(&g_k2[col], ak0);
    atomicAdd(&g_k2[HH + col], ak1);
    atomicAdd(&g_v2[col], av0);
    atomicAdd(&g_v2[HH + col], av1);
}

// ---------------- cross attention (64 blocks, one per batch row) ----------
__global__ void cross_kernel() {
    int b = blockIdx.x, t = threadIdx.x;  // 256 threads
    __shared__ float red0[256], red1[256];
    const float* qp = g_q + b * HH;
    float d0 = 0.f, d1 = 0.f;
    for (int d = t; d < HH; d += 256) {
        float qv = qp[d];
        d0 += qv * g_k2[d];
        d1 += qv * g_k2[HH + d];
    }
    red0[t] = d0; red1[t] = d1;
    __syncthreads();
    for (int s = 128; s > 0; s >>= 1) {
        if (t < s) { red0[t] += red0[t + s]; red1[t] += red1[t + s]; }
        __syncthreads();
    }
    float x0 = red0[0] * (1.0f / 32.0f);
    float x1 = red1[0] * (1.0f / 32.0f);
    float m = fmaxf(x0, x1);
    float e0 = expf(x0 - m), e1 = expf(x1 - m);
    float inv = 1.f / (e0 + e1);
    float a0 = e0 * inv, a1 = e1 * inv;
    for (int d = t; d < HH; d += 256)
        g_fcx[b * HH + d] = a0 * g_v2[d] + a1 * g_v2[HH + d];
}

// ---------------- classifier head ----------------
__global__ void final_kernel(const float* __restrict__ Wc2, const float* __restrict__ bc2,
                             float* __restrict__ out, int out_size) {
    int b = blockIdx.x, t = threadIdx.x;
    float acc = 0.f;
    for (int d = t; d < DD; d += 256) acc += fmaxf(g_t1[b * DD + d], 0.f) * Wc2[d];
    __shared__ float red[256];
    red[t] = acc; __syncthreads();
    for (int s = 128; s > 0; s >>= 1) { if (t < s) red[t] += red[t + s]; __syncthreads(); }
    if (t == 0) {
        float y = 1.f / (1.f + expf(-(red[0] + bc2[0])));
        out[b] = y;
        if (64 + b < out_size) out[64 + b] = (y >= 0.5f) ? 1.f : 0.f;
    }
}

// ---------------- launch ----------------
extern "C" void kernel_launch(void* const* d_in, const int* in_sizes, int n_in,
                              void* d_out, int out_size) {
    const float* FC    = (const float*)d_in[0];
    const float* cc    = (const float*)d_in[1];
    const float* W1    = (const float*)d_in[2];
    const float* b1    = (const float*)d_in[3];
    const float* W2    = (const float*)d_in[4];
    const float* b2    = (const float*)d_in[5];
    const float* bn_g  = (const float*)d_in[6];
    const float* bn_b  = (const float*)d_in[7];
    const float* bn2_g = (const float*)d_in[8];
    const float* bn2_b = (const float*)d_in[9];
    const float* Wq    = (const float*)d_in[10];
    const float* bq    = (const float*)d_in[11];
    const float* Wk    = (const float*)d_in[12];
    const float* bk    = (const float*)d_in[13];
    const float* Wc1   = (const float*)d_in[14];
    const float* bc1   = (const float*)d_in[15];
    const float* Wc2   = (const float*)d_in[16];
    const float* bc2   = (const float*)d_in[17];
    float* out = (float*)d_out;

    cudaFuncSetAttribute(gemm_mma_kernel, cudaFuncAttributeMaxDynamicSharedMemorySize, GEMM_SMEM);

    init_off_kernel<<<ROI, 128>>>();                                        // 1
    init_misc_kernel<<<(NB * HH + 4 * HH + NB * DD + 255) / 256, 256>>>(bq, bk, bc1);  // 2
    w1t_kernel<<<dim3(FEATP / 32, DD / 32), dim3(32, 8)>>>(W1, b2);         // 3
    gather_kernel<<<dim3(4, BW), 256>>>(FC);                                // 4 (ncu slot)
    gemm_mma_kernel<<<dim3(8, 64), 256, GEMM_SMEM>>>(b1, W2);               // 5
    softmax_kernel<<<NB, 128>>>();
    pool_kernel<<<dim3((FEAT / 4 + 255) / 256, NB), 256>>>();
    bn_kernel<<<(FEAT + 255) / 256, 256>>>(cc, bn_g, bn_b, bn2_g, bn2_b);
    skinny_kernel<64><<<dim3(4, 104), 256>>>(0, FEATP, Wq, HH, 0, FEAT, HH);
    kv_kernel<<<dim3(4, 16), 256>>>(Wk, Wq);
    cross_kernel<<<NB, 256>>>();
    skinny_kernel<64><<<dim3(4, 16), 256>>>(2, HH, Wc1, DD, 3, HH, DD);
    skinny_kernel<64><<<dim3(4, 104), 256>>>(0, FEATP, Wc1 + (size_t)HH * DD, DD, 3, FEAT, DD);
    final_kernel<<<NB, 256>>>(Wc2, bc2, out, out_size);
}

// round 14
// speedup vs baseline: 1.3552x; 1.0449x over previous
#include <cuda_runtime.h>
#include <cuda_fp16.h>
#include <math.h>
#include <stdint.h>

#define ROI   116
#define FEAT  6670      // ROI*(ROI-1)/2
#define FEATP 6720      // padded to multiple of 64
#define NB    64        // batch
#define NW    128       // bags per batch
#define BW    8192      // NB*NW
#define DD    1024
#define HH    1024
#define NSTG64 (FEATP / 64)  // 105 K-stages of 64

// ---------------- scratch (device globals; no allocation) ----------------
__device__ __align__(16) __half g_bag[(size_t)BW * FEATP];   // 110 MB
__device__ __align__(16) __half g_w1th[(size_t)DD * FEATP];  // 13.8 MB  [N][K]
__device__ __align__(16) int g_off[FEATP];
__device__ float g_a[BW];
__device__ float g_att[BW];
__device__ float g_bagz0[NB * FEATP];
__device__ float g_bagz[NB * FEATP];
__device__ float g_ccn[2 * FEATP];
__device__ float g_q[NB * HH];
__device__ float g_k2[2 * HH];
__device__ float g_v2[2 * HH];
__device__ float g_fcx[NB * HH];
__device__ float g_t1[NB * DD];

// ---------------- PTX helpers (generic, sm_80-level) ----------------
__device__ __forceinline__ uint32_t smem_u32(const void* p) {
    uint32_t a;
    asm("{ .reg .u64 t; cvta.to.shared.u64 t, %1; cvt.u32.u64 %0, t; }" : "=r"(a) : "l"(p));
    return a;
}
#define CP_ASYNC16(dst, src) \
    asm volatile("cp.async.cg.shared.global [%0], [%1], 16;" \
                 :: "r"(dst), "l"(src) : "memory")
#define CP_COMMIT() asm volatile("cp.async.commit_group;" ::: "memory")
#define CP_WAIT(n)  asm volatile("cp.async.wait_group %0;" :: "n"(n) : "memory")

__device__ __forceinline__ void ldm_x4(uint32_t& r0, uint32_t& r1, uint32_t& r2, uint32_t& r3,
                                       uint32_t addr) {
    asm volatile("ldmatrix.sync.aligned.m8n8.x4.shared.b16 {%0,%1,%2,%3}, [%4];"
                 : "=r"(r0), "=r"(r1), "=r"(r2), "=r"(r3) : "r"(addr));
}
__device__ __forceinline__ void mma16816(float* c, const uint32_t* a, const uint32_t* b) {
    asm volatile(
        "mma.sync.aligned.m16n8k16.row.col.f32.f16.f16.f32 "
        "{%0,%1,%2,%3}, {%4,%5,%6,%7}, {%8,%9}, {%0,%1,%2,%3};"
        : "+f"(c[0]), "+f"(c[1]), "+f"(c[2]), "+f"(c[3])
        : "r"(a[0]), "r"(a[1]), "r"(a[2]), "r"(a[3]), "r"(b[0]), "r"(b[1]));
}
__device__ __forceinline__ float fast_tanh(float x) {
    float e = __expf(2.0f * x);
    return 1.0f - 2.0f / (e + 1.0f);
}

// ---------------- triu index table (padded to FEATP with 0) ----------------
__global__ void init_off_kernel() {
    int i = blockIdx.x;                      // 0..ROI-1
    if (i == ROI - 1) {                      // padding block
        for (int f = FEAT + threadIdx.x; f < FEATP; f += blockDim.x) g_off[f] = 0;
        return;
    }
    int base = i * (ROI - 1) - i * (i - 1) / 2;
    int cnt = ROI - 1 - i;
    for (int jj = threadIdx.x; jj < cnt; jj += blockDim.x)
        g_off[base + jj] = i * ROI + (i + 1 + jj);
}

// ---------------- init biases into accumulator buffers (post-GEMM ones) ----
__global__ void init_misc_kernel(const float* __restrict__ bq,
                                 const float* __restrict__ bk,
                                 const float* __restrict__ bc1) {
    int idx = blockIdx.x * 256 + threadIdx.x;
    if (idx < NB * HH) { g_q[idx] = bq[idx & (HH - 1)]; return; }
    idx -= NB * HH;
    if (idx < 2 * HH) { g_k2[idx] = bk[idx & (HH - 1)]; return; }
    idx -= 2 * HH;
    if (idx < 2 * HH) { g_v2[idx] = bq[idx & (HH - 1)]; return; }
    idx -= 2 * HH;
    if (idx < NB * DD) { g_t1[idx] = bc1[idx & (DD - 1)]; return; }
}

// ---------------- W1 -> W1T fp16 ([N][K], padded); also inits g_a = b2 ----
__global__ void w1t_kernel(const float* __restrict__ W1, const float* __restrict__ b2) {
    __shared__ float t[32][33];
    int kb = blockIdx.x * 32, nb = blockIdx.y * 32;
    int tx = threadIdx.x, ty = threadIdx.y;
    if (blockIdx.x == 0 && blockIdx.y == 0) {
        int tid = ty * 32 + tx;
        float v = b2[0];
        for (int i = tid; i < BW; i += 256) g_a[i] = v;
    }
#pragma unroll
    for (int i = 0; i < 32; i += 8) {
        int k = kb + ty + i;
        t[ty + i][tx] = (k < FEAT) ? W1[(size_t)k * DD + nb + tx] : 0.f;
    }
    __syncthreads();
#pragma unroll
    for (int i = 0; i < 32; i += 8) {
        float v = t[tx][ty + i];
        g_w1th[(size_t)(nb + ty + i) * FEATP + kb + tx] = __float2half_rn(v);
    }
}

// ---------------- gather -> fp16 (8 features per thread, 16B store) -------
__global__ void gather_kernel(const float* __restrict__ FC) {
    int bw = blockIdx.y;
    int f0 = (blockIdx.x * 256 + threadIdx.x) * 8;
    if (f0 >= FEATP) return;
    const float* src = FC + (size_t)bw * (ROI * ROI);
    int4 oa = *reinterpret_cast<const int4*>(g_off + f0);
    int4 ob = *reinterpret_cast<const int4*>(g_off + f0 + 4);
    __half h[8];
    h[0] = (f0 + 0 < FEAT) ? __float2half_rn(src[oa.x]) : __half(0.f);
    h[1] = (f0 + 1 < FEAT) ? __float2half_rn(src[oa.y]) : __half(0.f);
    h[2] = (f0 + 2 < FEAT) ? __float2half_rn(src[oa.z]) : __half(0.f);
    h[3] = (f0 + 3 < FEAT) ? __float2half_rn(src[oa.w]) : __half(0.f);
    h[4] = (f0 + 4 < FEAT) ? __float2half_rn(src[ob.x]) : __half(0.f);
    h[5] = (f0 + 5 < FEAT) ? __float2half_rn(src[ob.y]) : __half(0.f);
    h[6] = (f0 + 6 < FEAT) ? __float2half_rn(src[ob.z]) : __half(0.f);
    h[7] = (f0 + 7 < FEAT) ? __float2half_rn(src[ob.w]) : __half(0.f);
    *reinterpret_cast<float4*>(g_bag + (size_t)bw * FEATP + f0) =
        *reinterpret_cast<const float4*>(h);
}

// ---------------- HMMA GEMM: S = bag @ W1T^T (fp16), fused tanh/W2 epi ----
#define LDA       144
#define TILE_B    18432               // 128 rows x 144B
#define STAGE_B   (2 * TILE_B)        // A + B = 36864
#define GEMM_SMEM (3 * STAGE_B)       // 110592

__device__ __forceinline__ void load_stage(uint32_t sdst, int k0, int m0, int n0, int tid) {
    int row = tid >> 1;
    int cb = (tid & 1) * 64;          // byte offset within 128B row half
    uint32_t so = sdst + row * LDA + cb;
    size_t ga = ((size_t)(m0 + row) * FEATP + k0) * 2 + cb;
    size_t gb = ((size_t)(n0 + row) * FEATP + k0) * 2 + cb;
    unsigned long long pa = __cvta_generic_to_global((const char*)g_bag + ga);
    unsigned long long pb = __cvta_generic_to_global((const char*)g_w1th + gb);
    CP_ASYNC16(so,      pa);      CP_ASYNC16(so + 16, pa + 16);
    CP_ASYNC16(so + 32, pa + 32); CP_ASYNC16(so + 48, pa + 48);
    so += TILE_B;
    CP_ASYNC16(so,      pb);      CP_ASYNC16(so + 16, pb + 16);
    CP_ASYNC16(so + 32, pb + 32); CP_ASYNC16(so + 48, pb + 48);
}

__global__ __launch_bounds__(256, 2) void gemm_mma_kernel(const float* __restrict__ b1,
                                                          const float* __restrict__ W2) {
    extern __shared__ char sm[];
    const uint32_t sbase = smem_u32(sm);
    const int tid = threadIdx.x, lane = tid & 31, wid = tid >> 5;
    const int wm = wid & 3, wn = wid >> 2;        // 4 M-warps x 2 N-warps
    const int n0 = blockIdx.x * 128, m0 = blockIdx.y * 128;

    float acc[2][8][4];
#pragma unroll
    for (int mt = 0; mt < 2; mt++)
#pragma unroll
        for (int nt = 0; nt < 8; nt++)
#pragma unroll
            for (int c = 0; c < 4; c++) acc[mt][nt][c] = 0.f;

    load_stage(sbase, 0, m0, n0, tid);             CP_COMMIT();
    load_stage(sbase + STAGE_B, 64, m0, n0, tid);  CP_COMMIT();

    const uint32_t aRowOfs = (uint32_t)(wm * 32 + ((lane >> 3) & 1) * 8 + (lane & 7)) * LDA
                           + (uint32_t)(lane >> 4) * 16;
    const uint32_t bRowOfs = (uint32_t)(wn * 64 + (lane >> 4) * 8 + (lane & 7)) * LDA
                           + (uint32_t)((lane >> 3) & 1) * 16;

    int slot = 0;
    for (int i = 0; i < NSTG64; i++) {
        if (i + 1 < NSTG64) { CP_WAIT(1); } else { CP_WAIT(0); }
        __syncthreads();
        if (i + 2 < NSTG64) {
            int ns = slot + 2; if (ns >= 3) ns -= 3;
            load_stage(sbase + (uint32_t)ns * STAGE_B, (i + 2) * 64, m0, n0, tid);
            CP_COMMIT();
        }
        const uint32_t st = sbase + (uint32_t)slot * STAGE_B;
#pragma unroll
        for (int kk = 0; kk < 4; kk++) {
            uint32_t aH[2][4], bb[8][2];
#pragma unroll
            for (int mt = 0; mt < 2; mt++)
                ldm_x4(aH[mt][0], aH[mt][1], aH[mt][2], aH[mt][3],
                       st + aRowOfs + (uint32_t)mt * 16 * LDA + kk * 32);
#pragma unroll
            for (int p = 0; p < 4; p++)
                ldm_x4(bb[2 * p][0], bb[2 * p][1], bb[2 * p + 1][0], bb[2 * p + 1][1],
                       st + TILE_B + bRowOfs + (uint32_t)p * 16 * LDA + kk * 32);
#pragma unroll
            for (int mt = 0; mt < 2; mt++)
#pragma unroll
                for (int nt = 0; nt < 8; nt++) mma16816(acc[mt][nt], aH[mt], bb[nt]);
        }
        if (++slot == 3) slot = 0;
    }

    // epilogue: per-row sum over n of tanh(S + b1)*W2, reduce, atomicAdd
    const int g = lane >> 2, t4 = lane & 3;
#pragma unroll
    for (int mt = 0; mt < 2; mt++) {
        float sA = 0.f, sB = 0.f;
#pragma unroll
        for (int nt = 0; nt < 8; nt++) {
            int c0 = n0 + wn * 64 + nt * 8 + 2 * t4;
            float b1a = b1[c0], b1b = b1[c0 + 1];
            float w2a = W2[c0], w2b = W2[c0 + 1];
            sA += fast_tanh(acc[mt][nt][0] + b1a) * w2a + fast_tanh(acc[mt][nt][1] + b1b) * w2b;
            sB += fast_tanh(acc[mt][nt][2] + b1a) * w2a + fast_tanh(acc[mt][nt][3] + b1b) * w2b;
        }
        sA += __shfl_xor_sync(0xFFFFFFFF, sA, 1);
        sA += __shfl_xor_sync(0xFFFFFFFF, sA, 2);
        sB += __shfl_xor_sync(0xFFFFFFFF, sB, 1);
        sB += __shfl_xor_sync(0xFFFFFFFF, sB, 2);
        if (t4 == 0) {
            int r = m0 + wm * 32 + mt * 16 + g;
            atomicAdd(&g_a[r], sA);
            atomicAdd(&g_a[r + 8], sB);
        }
    }
}

// ---------------- softmax over W per batch ----------------
__global__ void softmax_kernel() {
    int b = blockIdx.x, t = threadIdx.x;  // 128 threads
    __shared__ float sv[128];
    float v = g_a[b * NW + t];
    sv[t] = v; __syncthreads();
    for (int s = 64; s > 0; s >>= 1) { if (t < s) sv[t] = fmaxf(sv[t], sv[t + s]); __syncthreads(); }
    float m = sv[0]; __syncthreads();
    float e = expf(v - m);
    sv[t] = e; __syncthreads();
    for (int s = 64; s > 0; s >>= 1) { if (t < s) sv[t] += sv[t + s]; __syncthreads(); }
    g_att[b * NW + t] = e / sv[0];
}

// ---------------- attention pool (8 features per thread, 16B loads) -------
__global__ void pool_kernel() {
    int b = blockIdx.y;
    int f0 = (blockIdx.x * 256 + threadIdx.x) * 8;
    __shared__ float sat[NW];
    if (threadIdx.x < NW) sat[threadIdx.x] = g_att[b * NW + threadIdx.x];
    __syncthreads();
    if (f0 >= FEAT) return;
    float a[8];
#pragma unroll
    for (int j = 0; j < 8; j++) a[j] = 0.f;
    const char* base = (const char*)(g_bag + (size_t)b * NW * FEATP + f0);
#pragma unroll 2
    for (int w = 0; w < NW; w++) {
        float4 raw = *reinterpret_cast<const float4*>(base + (size_t)w * (FEATP * 2));
        const __half2* hp = reinterpret_cast<const __half2*>(&raw);
        float aw = sat[w];
#pragma unroll
        for (int j = 0; j < 4; j++) {
            float2 v = __half22float2(hp[j]);
            a[2 * j]     += aw * v.x;
            a[2 * j + 1] += aw * v.y;
        }
    }
    float* dst = g_bagz0 + (size_t)b * FEATP + f0;
    if (f0 + 7 < FEAT) {
        *reinterpret_cast<float4*>(dst)     = make_float4(a[0], a[1], a[2], a[3]);
        *reinterpret_cast<float4*>(dst + 4) = make_float4(a[4], a[5], a[6], a[7]);
    } else {
#pragma unroll
        for (int j = 0; j < 8; j++)
            if (f0 + j < FEAT) dst[j] = a[j];
    }
}

// ---------------- batchnorms ----------------
__global__ void bn_kernel(const float* __restrict__ cc,
                          const float* __restrict__ bn_g, const float* __restrict__ bn_b,
                          const float* __restrict__ bn2_g, const float* __restrict__ bn2_b) {
    int f = blockIdx.x * 256 + threadIdx.x;
    if (f >= FEAT) return;
    float mu = 0.f;
    for (int b = 0; b < NB; b++) mu += g_bagz0[b * FEATP + f];
    mu *= (1.f / NB);
    float var = 0.f;
    for (int b = 0; b < NB; b++) { float d = g_bagz0[b * FEATP + f] - mu; var += d * d; }
    var *= (1.f / NB);
    float inv = rsqrtf(var + 1e-5f);
    float g = bn_g[f], bt = bn_b[f];
    for (int b = 0; b < NB; b++)
        g_bagz[b * FEATP + f] = (g_bagz0[b * FEATP + f] - mu) * inv * g + bt;
    float c0 = cc[f], c1 = cc[FEAT + f];
    float mu2 = 0.5f * (c0 + c1);
    float d0 = c0 - mu2, d1 = c1 - mu2;
    float inv2 = rsqrtf(0.5f * (d0 * d0 + d1 * d1) + 1e-5f);
    float g2 = bn2_g[f], b2v = bn2_b[f];
    g_ccn[f] = d0 * inv2 * g2 + b2v;
    g_ccn[FEATP + f] = d1 * inv2 * g2 + b2v;
}

// ---------------- dual skinny: q += bagz@Wq ; t1 += bagz@Wc1[HH:] ----------
// M=32 per block (grid.z picks half), K split by grid.y, shared sA staging.
__global__ __launch_bounds__(256) void skinny_dual_kernel(const float* __restrict__ B1,
                                                          const float* __restrict__ B2) {
    __shared__ float sA[32][33];
    int tid = threadIdx.x;
    int col = blockIdx.x * 256 + tid;   // < HH (= DD)
    int m0 = blockIdx.z * 32;
    int nsplit = gridDim.y;
    int len = (FEAT + nsplit - 1) / nsplit;
    int k0 = blockIdx.y * len;
    int kend = min(FEAT, k0 + len);
    float aq[32], at[32];
#pragma unroll
    for (int m = 0; m < 32; m++) { aq[m] = 0.f; at[m] = 0.f; }
    for (int kb = k0; kb < kend; kb += 32) {
        int kmax = min(32, kend - kb);
        for (int idx = tid; idx < 32 * 32; idx += 256) {
            int m = idx >> 5, kk = idx & 31;
            sA[m][kk] = (kk < kmax) ? g_bagz[(size_t)(m0 + m) * FEATP + kb + kk] : 0.f;
        }
        __syncthreads();
        const float* P1 = B1 + (size_t)kb * HH + col;
        const float* P2 = B2 + (size_t)kb * DD + col;
        int kk = 0;
        for (; kk + 2 <= kmax; kk += 2) {
            float q0 = P1[0], q1 = P1[HH];
            float t0 = P2[0], t1v = P2[DD];
            P1 += 2 * HH; P2 += 2 * DD;
#pragma unroll
            for (int m = 0; m < 32; m++) aq[m] += sA[m][kk] * q0;
#pragma unroll
            for (int m = 0; m < 32; m++) at[m] += sA[m][kk] * t0;
#pragma unroll
            for (int m = 0; m < 32; m++) aq[m] += sA[m][kk + 1] * q1;
#pragma unroll
            for (int m = 0; m < 32; m++) at[m] += sA[m][kk + 1] * t1v;
        }
        for (; kk < kmax; kk++) {
            float q0 = P1[0], t0 = P2[0]; P1 += HH; P2 += DD;
#pragma unroll
            for (int m = 0; m < 32; m++) { aq[m] += sA[m][kk] * q0; at[m] += sA[m][kk] * t0; }
        }
        __syncthreads();
    }
#pragma unroll
    for (int m = 0; m < 32; m++) {
        atomicAdd(&g_q[(size_t)(m0 + m) * HH + col], aq[m]);
        atomicAdd(&g_t1[(size_t)(m0 + m) * DD + col], at[m]);
    }
}

// ---------------- skinny GEMM (fcx part): t1 += fcx@Wc1[0:HH] --------------
__global__ __launch_bounds__(256) void skinny_fcx_kernel(const float* __restrict__ B) {
    __shared__ float sA[64][33];
    int tid = threadIdx.x;
    int col = blockIdx.x * 256 + tid;
    int nsplit = gridDim.y;
    int len = (HH + nsplit - 1) / nsplit;
    int k0 = blockIdx.y * len;
    int kend = min(HH, k0 + len);
    float acc[64];
#pragma unroll
    for (int m = 0; m < 64; m++) acc[m] = 0.f;
    for (int kb = k0; kb < kend; kb += 32) {
        int kmax = min(32, kend - kb);
        for (int idx = tid; idx < 64 * 32; idx += 256) {
            int m = idx >> 5, kk = idx & 31;
            sA[m][kk] = (kk < kmax) ? g_fcx[(size_t)m * HH + kb + kk] : 0.f;
        }
        __syncthreads();
        const float* Bp = B + (size_t)kb * DD + col;
        int kk = 0;
        for (; kk + 4 <= kmax; kk += 4) {
            float bv0 = Bp[0];
            float bv1 = Bp[DD];
            float bv2 = Bp[2 * DD];
            float bv3 = Bp[3 * DD];
            Bp += 4 * (size_t)DD;
#pragma unroll
            for (int m = 0; m < 64; m++) acc[m] += sA[m][kk] * bv0;
#pragma unroll
            for (int m = 0; m < 64; m++) acc[m] += sA[m][kk + 1] * bv1;
#pragma unroll
            for (int m = 0; m < 64; m++) acc[m] += sA[m][kk + 2] * bv2;
#pragma unroll
            for (int m = 0; m < 64; m++) acc[m] += sA[m][kk + 3] * bv3;
        }
        for (; kk < kmax; kk++) {
            float bv = Bp[0]; Bp += (size_t)DD;
#pragma unroll
            for (int m = 0; m < 64; m++) acc[m] += sA[m][kk] * bv;
        }
        __syncthreads();
    }
#pragma unroll
    for (int m = 0; m < 64; m++) atomicAdd(&g_t1[(size_t)m * DD + col], acc[m]);
}

// ---------------- merged k/v skinny: k2 += ccn@Wk, v2 += ccn@Wq ----------------
__global__ __launch_bounds__(256) void kv_kernel(const float* __restrict__ Wk,
                                                 const float* __restrict__ Wq) {
    __shared__ float sA[2][33];
    int tid = threadIdx.x;
    int col = blockIdx.x * 256 + tid;   // < HH
    int nsplit = gridDim.y;
    int len = (FEAT + nsplit - 1) / nsplit;
    int k0 = blockIdx.y * len;
    int kend = min(FEAT, k0 + len);
    float ak0 = 0.f, ak1 = 0.f, av0 = 0.f, av1 = 0.f;
    for (int kb = k0; kb < kend; kb += 32) {
        int kmax = min(32, kend - kb);
        if (tid < 64) {
            int m = tid >> 5, kk = tid & 31;
            sA[m][kk] = (kk < kmax) ? g_ccn[(size_t)m * FEATP + kb + kk] : 0.f;
        }
        __syncthreads();
        const float* Kp = Wk + (size_t)kb * HH + col;
        const float* Qp = Wq + (size_t)kb * HH + col;
        int kk = 0;
        for (; kk + 2 <= kmax; kk += 2) {
            float k0v = Kp[0], k1v = Kp[HH];
            float q0v = Qp[0], q1v = Qp[HH];
            Kp += 2 * HH; Qp += 2 * HH;
            ak0 += sA[0][kk] * k0v; ak1 += sA[1][kk] * k0v;
            av0 += sA[0][kk] * q0v; av1 += sA[1][kk] * q0v;
            ak0 += sA[0][kk + 1] * k1v; ak1 += sA[1][kk + 1] * k1v;
            av0 += sA[0][kk + 1] * q1v; av1 += sA[1][kk + 1] * q1v;
        }
        for (; kk < kmax; kk++) {
            float kv = Kp[0], qv = Qp[0]; Kp += HH; Qp += HH;
            ak0 += sA[0][kk] * kv; ak1 += sA[1][kk] * kv;
            av0 += sA[0][kk] * qv; av1 += sA[1][kk] * qv;
        }
        __syncthreads();
    }
    atomicAdd(&g_k2[col], ak0);
    atomicAdd(&g_k2[HH + col], ak1);
    atomicAdd(&g_v2[col], av0);
    atomicAdd(&g_v2[HH + col], av1);
}

// ---------------- cross attention (64 blocks, one per batch row) ----------
__global__ void cross_kernel() {
    int b = blockIdx.x, t = threadIdx.x;  // 256 threads
    __shared__ float red0[256], red1[256];
    const float* qp = g_q + b * HH;
    float d0 = 0.f, d1 = 0.f;
    for (int d = t; d < HH; d += 256) {
        float qv = qp[d];
        d0 += qv * g_k2[d];
        d1 += qv * g_k2[HH + d];
    }
    red0[t] = d0; red1[t] = d1;
    __syncthreads();
    for (int s = 128; s > 0; s >>= 1) {
        if (t < s) { red0[t] += red0[t + s]; red1[t] += red1[t + s]; }
        __syncthreads();
    }
    float x0 = red0[0] * (1.0f / 32.0f);
    float x1 = red1[0] * (1.0f / 32.0f);
    float m = fmaxf(x0, x1);
    float e0 = expf(x0 - m), e1 = expf(x1 - m);
    float inv = 1.f / (e0 + e1);
    float a0 = e0 * inv, a1 = e1 * inv;
    for (int d = t; d < HH; d += 256)
        g_fcx[b * HH + d] = a0 * g_v2[d] + a1 * g_v2[HH + d];
}

// ---------------- classifier head ----------------
__global__ void final_kernel(const float* __restrict__ Wc2, const float* __restrict__ bc2,
                             float* __restrict__ out, int out_size) {
    int b = blockIdx.x, t = threadIdx.x;
    float acc = 0.f;
    for (int d = t; d < DD; d += 256) acc += fmaxf(g_t1[b * DD + d], 0.f) * Wc2[d];
    __shared__ float red[256];
    red[t] = acc; __syncthreads();
    for (int s = 128; s > 0; s >>= 1) { if (t < s) red[t] += red[t + s]; __syncthreads(); }
    if (t == 0) {
        float y = 1.f / (1.f + expf(-(red[0] + bc2[0])));
        out[b] = y;
        if (64 + b < out_size) out[64 + b] = (y >= 0.5f) ? 1.f : 0.f;
    }
}

// ---------------- launch ----------------
extern "C" void kernel_launch(void* const* d_in, const int* in_sizes, int n_in,
                              void* d_out, int out_size) {
    const float* FC    = (const float*)d_in[0];
    const float* cc    = (const float*)d_in[1];
    const float* W1    = (const float*)d_in[2];
    const float* b1    = (const float*)d_in[3];
    const float* W2    = (const float*)d_in[4];
    const float* b2    = (const float*)d_in[5];
    const float* bn_g  = (const float*)d_in[6];
    const float* bn_b  = (const float*)d_in[7];
    const float* bn2_g = (const float*)d_in[8];
    const float* bn2_b = (const float*)d_in[9];
    const float* Wq    = (const float*)d_in[10];
    const float* bq    = (const float*)d_in[11];
    const float* Wk    = (const float*)d_in[12];
    const float* bk    = (const float*)d_in[13];
    const float* Wc1   = (const float*)d_in[14];
    const float* bc1   = (const float*)d_in[15];
    const float* Wc2   = (const float*)d_in[16];
    const float* bc2   = (const float*)d_in[17];
    float* out = (float*)d_out;

    cudaFuncSetAttribute(gemm_mma_kernel, cudaFuncAttributeMaxDynamicSharedMemorySize, GEMM_SMEM);

    init_off_kernel<<<ROI, 128>>>();                                        // 1
    init_misc_kernel<<<(NB * HH + 4 * HH + NB * DD + 255) / 256, 256>>>(bq, bk, bc1);  // 2
    w1t_kernel<<<dim3(FEATP / 32, DD / 32), dim3(32, 8)>>>(W1, b2);         // 3
    gather_kernel<<<dim3(4, BW), 256>>>(FC);                                // 4 (ncu slot)
    gemm_mma_kernel<<<dim3(8, 64), 256, GEMM_SMEM>>>(b1, W2);               // 5
    softmax_kernel<<<NB, 128>>>();
    pool_kernel<<<dim3(4, NB), 256>>>();
    bn_kernel<<<(FEAT + 255) / 256, 256>>>(cc, bn_g, bn_b, bn2_g, bn2_b);
    skinny_dual_kernel<<<dim3(4, 104, 2), 256>>>(Wq, Wc1 + (size_t)HH * DD);
    kv_kernel<<<dim3(4, 16), 256>>>(Wk, Wq);
    cross_kernel<<<NB, 256>>>();
    skinny_fcx_kernel<<<dim3(4, 16), 256>>>(Wc1);
    final_kernel<<<NB, 256>>>(Wc2, bc2, out, out_size);
}

// round 15
// speedup vs baseline: 1.4411x; 1.0634x over previous
#include <cuda_runtime.h>
#include <cuda_fp16.h>
#include <math.h>
#include <stdint.h>

#define ROI   116
#define FEAT  6670      // ROI*(ROI-1)/2
#define FEATP 6720      // padded to multiple of 64
#define NB    64        // batch
#define NW    128       // bags per batch
#define BW    8192      // NB*NW
#define DD    1024
#define HH    1024
#define NSTG64 (FEATP / 64)  // 105 K-stages of 64
#define INIT_ELEMS (NB * HH + 2 * HH + 2 * HH + NB * DD)   // 135168
#define INIT_BLOCKS ((INIT_ELEMS + 255) / 256)             // 528

// ---------------- scratch (device globals; no allocation) ----------------
__device__ __align__(16) __half g_bag[(size_t)BW * FEATP];   // 110 MB
__device__ __align__(16) __half g_w1th[(size_t)DD * FEATP];  // 13.8 MB  [N][K]
__device__ __align__(16) int g_off[FEATP];
__device__ float g_a[BW];
__device__ float g_bagz0[NB * FEATP];
__device__ float g_bagz[NB * FEATP];
__device__ float g_ccn[2 * FEATP];
__device__ float g_q[NB * HH];
__device__ float g_k2[2 * HH];
__device__ float g_v2[2 * HH];
__device__ float g_fcx[NB * HH];
__device__ float g_t1[NB * DD];

// ---------------- PTX helpers (generic, sm_80-level) ----------------
__device__ __forceinline__ uint32_t smem_u32(const void* p) {
    uint32_t a;
    asm("{ .reg .u64 t; cvta.to.shared.u64 t, %1; cvt.u32.u64 %0, t; }" : "=r"(a) : "l"(p));
    return a;
}
#define CP_ASYNC16(dst, src) \
    asm volatile("cp.async.cg.shared.global [%0], [%1], 16;" \
                 :: "r"(dst), "l"(src) : "memory")
#define CP_COMMIT() asm volatile("cp.async.commit_group;" ::: "memory")
#define CP_WAIT(n)  asm volatile("cp.async.wait_group %0;" :: "n"(n) : "memory")

__device__ __forceinline__ void ldm_x4(uint32_t& r0, uint32_t& r1, uint32_t& r2, uint32_t& r3,
                                       uint32_t addr) {
    asm volatile("ldmatrix.sync.aligned.m8n8.x4.shared.b16 {%0,%1,%2,%3}, [%4];"
                 : "=r"(r0), "=r"(r1), "=r"(r2), "=r"(r3) : "r"(addr));
}
__device__ __forceinline__ void mma16816(float* c, const uint32_t* a, const uint32_t* b) {
    asm volatile(
        "mma.sync.aligned.m16n8k16.row.col.f32.f16.f16.f32 "
        "{%0,%1,%2,%3}, {%4,%5,%6,%7}, {%8,%9}, {%0,%1,%2,%3};"
        : "+f"(c[0]), "+f"(c[1]), "+f"(c[2]), "+f"(c[3])
        : "r"(a[0]), "r"(a[1]), "r"(a[2]), "r"(a[3]), "r"(b[0]), "r"(b[1]));
}
__device__ __forceinline__ float fast_tanh(float x) {
    float e = __expf(2.0f * x);
    return 1.0f - 2.0f / (e + 1.0f);
}

// ---------------- triu index table + bias-buffer init (fused) -------------
__global__ void init_off_kernel(const float* __restrict__ bq,
                                const float* __restrict__ bk,
                                const float* __restrict__ bc1) {
    int i = blockIdx.x;
    if (i < ROI - 1) {                        // triu table rows
        int base = i * (ROI - 1) - i * (i - 1) / 2;
        int cnt = ROI - 1 - i;
        for (int jj = threadIdx.x; jj < cnt; jj += blockDim.x)
            g_off[base + jj] = i * ROI + (i + 1 + jj);
        return;
    }
    if (i == ROI - 1) {                       // padding
        for (int f = FEAT + threadIdx.x; f < FEATP; f += blockDim.x) g_off[f] = 0;
        return;
    }
    int idx = (i - ROI) * 256 + threadIdx.x;  // bias init region
    if (idx < NB * HH) { g_q[idx] = bq[idx & (HH - 1)]; return; }
    idx -= NB * HH;
    if (idx < 2 * HH) { g_k2[idx] = bk[idx & (HH - 1)]; return; }
    idx -= 2 * HH;
    if (idx < 2 * HH) { g_v2[idx] = bq[idx & (HH - 1)]; return; }
    idx -= 2 * HH;
    if (idx < NB * DD) { g_t1[idx] = bc1[idx & (DD - 1)]; return; }
}

// ---------------- W1 -> W1T fp16 ([N][K], padded); also inits g_a = b2 ----
__global__ void w1t_kernel(const float* __restrict__ W1, const float* __restrict__ b2) {
    __shared__ float t[32][33];
    int kb = blockIdx.x * 32, nb = blockIdx.y * 32;
    int tx = threadIdx.x, ty = threadIdx.y;
    if (blockIdx.x == 0 && blockIdx.y == 0) {
        int tid = ty * 32 + tx;
        float v = b2[0];
        for (int i = tid; i < BW; i += 256) g_a[i] = v;
    }
#pragma unroll
    for (int i = 0; i < 32; i += 8) {
        int k = kb + ty + i;
        t[ty + i][tx] = (k < FEAT) ? W1[(size_t)k * DD + nb + tx] : 0.f;
    }
    __syncthreads();
#pragma unroll
    for (int i = 0; i < 32; i += 8) {
        float v = t[tx][ty + i];
        g_w1th[(size_t)(nb + ty + i) * FEATP + kb + tx] = __float2half_rn(v);
    }
}

// ---------------- gather -> fp16 (8 features per thread, 16B store) -------
__global__ void gather_kernel(const float* __restrict__ FC) {
    int bw = blockIdx.y;
    int f0 = (blockIdx.x * 256 + threadIdx.x) * 8;
    if (f0 >= FEATP) return;
    const float* src = FC + (size_t)bw * (ROI * ROI);
    int4 oa = *reinterpret_cast<const int4*>(g_off + f0);
    int4 ob = *reinterpret_cast<const int4*>(g_off + f0 + 4);
    __half h[8];
    h[0] = (f0 + 0 < FEAT) ? __float2half_rn(src[oa.x]) : __half(0.f);
    h[1] = (f0 + 1 < FEAT) ? __float2half_rn(src[oa.y]) : __half(0.f);
    h[2] = (f0 + 2 < FEAT) ? __float2half_rn(src[oa.z]) : __half(0.f);
    h[3] = (f0 + 3 < FEAT) ? __float2half_rn(src[oa.w]) : __half(0.f);
    h[4] = (f0 + 4 < FEAT) ? __float2half_rn(src[ob.x]) : __half(0.f);
    h[5] = (f0 + 5 < FEAT) ? __float2half_rn(src[ob.y]) : __half(0.f);
    h[6] = (f0 + 6 < FEAT) ? __float2half_rn(src[ob.z]) : __half(0.f);
    h[7] = (f0 + 7 < FEAT) ? __float2half_rn(src[ob.w]) : __half(0.f);
    *reinterpret_cast<float4*>(g_bag + (size_t)bw * FEATP + f0) =
        *reinterpret_cast<const float4*>(h);
}

// ---------------- HMMA GEMM: S = bag @ W1T^T (fp16), fused tanh/W2 epi ----
#define LDA       144
#define TILE_B    18432               // 128 rows x 144B
#define STAGE_B   (2 * TILE_B)        // A + B = 36864
#define GEMM_SMEM (3 * STAGE_B)       // 110592

__device__ __forceinline__ void load_stage(uint32_t sdst, int k0, int m0, int n0, int tid) {
    int row = tid >> 1;
    int cb = (tid & 1) * 64;          // byte offset within 128B row half
    uint32_t so = sdst + row * LDA + cb;
    size_t ga = ((size_t)(m0 + row) * FEATP + k0) * 2 + cb;
    size_t gb = ((size_t)(n0 + row) * FEATP + k0) * 2 + cb;
    unsigned long long pa = __cvta_generic_to_global((const char*)g_bag + ga);
    unsigned long long pb = __cvta_generic_to_global((const char*)g_w1th + gb);
    CP_ASYNC16(so,      pa);      CP_ASYNC16(so + 16, pa + 16);
    CP_ASYNC16(so + 32, pa + 32); CP_ASYNC16(so + 48, pa + 48);
    so += TILE_B;
    CP_ASYNC16(so,      pb);      CP_ASYNC16(so + 16, pb + 16);
    CP_ASYNC16(so + 32, pb + 32); CP_ASYNC16(so + 48, pb + 48);
}

__global__ __launch_bounds__(256, 2) void gemm_mma_kernel(const float* __restrict__ b1,
                                                          const float* __restrict__ W2) {
    extern __shared__ char sm[];
    const uint32_t sbase = smem_u32(sm);
    const int tid = threadIdx.x, lane = tid & 31, wid = tid >> 5;
    const int wm = wid & 3, wn = wid >> 2;        // 4 M-warps x 2 N-warps
    const int n0 = blockIdx.x * 128, m0 = blockIdx.y * 128;

    float acc[2][8][4];
#pragma unroll
    for (int mt = 0; mt < 2; mt++)
#pragma unroll
        for (int nt = 0; nt < 8; nt++)
#pragma unroll
            for (int c = 0; c < 4; c++) acc[mt][nt][c] = 0.f;

    load_stage(sbase, 0, m0, n0, tid);             CP_COMMIT();
    load_stage(sbase + STAGE_B, 64, m0, n0, tid);  CP_COMMIT();

    const uint32_t aRowOfs = (uint32_t)(wm * 32 + ((lane >> 3) & 1) * 8 + (lane & 7)) * LDA
                           + (uint32_t)(lane >> 4) * 16;
    const uint32_t bRowOfs = (uint32_t)(wn * 64 + (lane >> 4) * 8 + (lane & 7)) * LDA
                           + (uint32_t)((lane >> 3) & 1) * 16;

    int slot = 0;
    for (int i = 0; i < NSTG64; i++) {
        if (i + 1 < NSTG64) { CP_WAIT(1); } else { CP_WAIT(0); }
        __syncthreads();
        if (i + 2 < NSTG64) {
            int ns = slot + 2; if (ns >= 3) ns -= 3;
            load_stage(sbase + (uint32_t)ns * STAGE_B, (i + 2) * 64, m0, n0, tid);
            CP_COMMIT();
        }
        const uint32_t st = sbase + (uint32_t)slot * STAGE_B;
#pragma unroll
        for (int kk = 0; kk < 4; kk++) {
            uint32_t aH[2][4], bb[8][2];
#pragma unroll
            for (int mt = 0; mt < 2; mt++)
                ldm_x4(aH[mt][0], aH[mt][1], aH[mt][2], aH[mt][3],
                       st + aRowOfs + (uint32_t)mt * 16 * LDA + kk * 32);
#pragma unroll
            for (int p = 0; p < 4; p++)
                ldm_x4(bb[2 * p][0], bb[2 * p][1], bb[2 * p + 1][0], bb[2 * p + 1][1],
                       st + TILE_B + bRowOfs + (uint32_t)p * 16 * LDA + kk * 32);
#pragma unroll
            for (int mt = 0; mt < 2; mt++)
#pragma unroll
                for (int nt = 0; nt < 8; nt++) mma16816(acc[mt][nt], aH[mt], bb[nt]);
        }
        if (++slot == 3) slot = 0;
    }

    // epilogue: per-row sum over n of tanh(S + b1)*W2, reduce, atomicAdd
    const int g = lane >> 2, t4 = lane & 3;
#pragma unroll
    for (int mt = 0; mt < 2; mt++) {
        float sA = 0.f, sB = 0.f;
#pragma unroll
        for (int nt = 0; nt < 8; nt++) {
            int c0 = n0 + wn * 64 + nt * 8 + 2 * t4;
            float b1a = b1[c0], b1b = b1[c0 + 1];
            float w2a = W2[c0], w2b = W2[c0 + 1];
            sA += fast_tanh(acc[mt][nt][0] + b1a) * w2a + fast_tanh(acc[mt][nt][1] + b1b) * w2b;
            sB += fast_tanh(acc[mt][nt][2] + b1a) * w2a + fast_tanh(acc[mt][nt][3] + b1b) * w2b;
        }
        sA += __shfl_xor_sync(0xFFFFFFFF, sA, 1);
        sA += __shfl_xor_sync(0xFFFFFFFF, sA, 2);
        sB += __shfl_xor_sync(0xFFFFFFFF, sB, 1);
        sB += __shfl_xor_sync(0xFFFFFFFF, sB, 2);
        if (t4 == 0) {
            int r = m0 + wm * 32 + mt * 16 + g;
            atomicAdd(&g_a[r], sA);
            atomicAdd(&g_a[r + 8], sB);
        }
    }
}

// ---------------- pool with in-block softmax (8 features per thread) ------
__global__ void pool_kernel() {
    int b = blockIdx.y;
    int t = threadIdx.x;
    int f0 = (blockIdx.x * 256 + t) * 8;
    __shared__ float sat[NW];
    __shared__ float red[NW];
    float v = 0.f;
    if (t < NW) { v = g_a[b * NW + t]; red[t] = v; }
    __syncthreads();
    for (int s = 64; s > 0; s >>= 1) { if (t < s) red[t] = fmaxf(red[t], red[t + s]); __syncthreads(); }
    float m = red[0];
    __syncthreads();
    float e = 0.f;
    if (t < NW) { e = expf(v - m); red[t] = e; }
    __syncthreads();
    for (int s = 64; s > 0; s >>= 1) { if (t < s) red[t] += red[t + s]; __syncthreads(); }
    if (t < NW) sat[t] = e / red[0];
    __syncthreads();
    if (f0 >= FEAT) return;
    float a[8];
#pragma unroll
    for (int j = 0; j < 8; j++) a[j] = 0.f;
    const char* base = (const char*)(g_bag + (size_t)b * NW * FEATP + f0);
#pragma unroll 2
    for (int w = 0; w < NW; w++) {
        float4 raw = *reinterpret_cast<const float4*>(base + (size_t)w * (FEATP * 2));
        const __half2* hp = reinterpret_cast<const __half2*>(&raw);
        float aw = sat[w];
#pragma unroll
        for (int j = 0; j < 4; j++) {
            float2 vv = __half22float2(hp[j]);
            a[2 * j]     += aw * vv.x;
            a[2 * j + 1] += aw * vv.y;
        }
    }
    float* dst = g_bagz0 + (size_t)b * FEATP + f0;
    if (f0 + 7 < FEAT) {
        *reinterpret_cast<float4*>(dst)     = make_float4(a[0], a[1], a[2], a[3]);
        *reinterpret_cast<float4*>(dst + 4) = make_float4(a[4], a[5], a[6], a[7]);
    } else {
#pragma unroll
        for (int j = 0; j < 8; j++)
            if (f0 + j < FEAT) dst[j] = a[j];
    }
}

// ---------------- batchnorms ----------------
__global__ void bn_kernel(const float* __restrict__ cc,
                          const float* __restrict__ bn_g, const float* __restrict__ bn_b,
                          const float* __restrict__ bn2_g, const float* __restrict__ bn2_b) {
    int f = blockIdx.x * 256 + threadIdx.x;
    if (f >= FEAT) return;
    float mu = 0.f;
    for (int b = 0; b < NB; b++) mu += g_bagz0[b * FEATP + f];
    mu *= (1.f / NB);
    float var = 0.f;
    for (int b = 0; b < NB; b++) { float d = g_bagz0[b * FEATP + f] - mu; var += d * d; }
    var *= (1.f / NB);
    float inv = rsqrtf(var + 1e-5f);
    float g = bn_g[f], bt = bn_b[f];
    for (int b = 0; b < NB; b++)
        g_bagz[b * FEATP + f] = (g_bagz0[b * FEATP + f] - mu) * inv * g + bt;
    float c0 = cc[f], c1 = cc[FEAT + f];
    float mu2 = 0.5f * (c0 + c1);
    float d0 = c0 - mu2, d1 = c1 - mu2;
    float inv2 = rsqrtf(0.5f * (d0 * d0 + d1 * d1) + 1e-5f);
    float g2 = bn2_g[f], b2v = bn2_b[f];
    g_ccn[f] = d0 * inv2 * g2 + b2v;
    g_ccn[FEATP + f] = d1 * inv2 * g2 + b2v;
}

// ---------------- dual skinny + kv (fused): -------------------------------
// z=0,1: q += bagz@Wq ; t1 += bagz@Wc1[HH:]  (M=32 halves)
// z=2:   k2 += ccn@Wk ; v2 += ccn@Wq         (y<16 active)
__global__ __launch_bounds__(256) void skinny_dual_kernel(const float* __restrict__ B1,
                                                          const float* __restrict__ B2,
                                                          const float* __restrict__ Wk) {
    __shared__ float sA[32][33];
    int tid = threadIdx.x;
    int col = blockIdx.x * 256 + tid;   // < HH (= DD)
    if (blockIdx.z == 2) {
        // ---- kv path ----
        if (blockIdx.y >= 16) return;
        int len = (FEAT + 15) / 16;
        int k0 = blockIdx.y * len;
        int kend = min(FEAT, k0 + len);
        float ak0 = 0.f, ak1 = 0.f, av0 = 0.f, av1 = 0.f;
        for (int kb = k0; kb < kend; kb += 32) {
            int kmax = min(32, kend - kb);
            if (tid < 64) {
                int m = tid >> 5, kk = tid & 31;
                sA[m][kk] = (kk < kmax) ? g_ccn[(size_t)m * FEATP + kb + kk] : 0.f;
            }
            __syncthreads();
            const float* Kp = Wk + (size_t)kb * HH + col;
            const float* Qp = B1 + (size_t)kb * HH + col;
            int kk = 0;
            for (; kk + 2 <= kmax; kk += 2) {
                float k0v = Kp[0], k1v = Kp[HH];
                float q0v = Qp[0], q1v = Qp[HH];
                Kp += 2 * HH; Qp += 2 * HH;
                ak0 += sA[0][kk] * k0v; ak1 += sA[1][kk] * k0v;
                av0 += sA[0][kk] * q0v; av1 += sA[1][kk] * q0v;
                ak0 += sA[0][kk + 1] * k1v; ak1 += sA[1][kk + 1] * k1v;
                av0 += sA[0][kk + 1] * q1v; av1 += sA[1][kk + 1] * q1v;
            }
            for (; kk < kmax; kk++) {
                float kv = Kp[0], qv = Qp[0]; Kp += HH; Qp += HH;
                ak0 += sA[0][kk] * kv; ak1 += sA[1][kk] * kv;
                av0 += sA[0][kk] * qv; av1 += sA[1][kk] * qv;
            }
            __syncthreads();
        }
        atomicAdd(&g_k2[col], ak0);
        atomicAdd(&g_k2[HH + col], ak1);
        atomicAdd(&g_v2[col], av0);
        atomicAdd(&g_v2[HH + col], av1);
        return;
    }
    // ---- dual bagz path ----
    int m0 = blockIdx.z * 32;
    int nsplit = gridDim.y;
    int len = (FEAT + nsplit - 1) / nsplit;
    int k0 = blockIdx.y * len;
    int kend = min(FEAT, k0 + len);
    float aq[32], at[32];
#pragma unroll
    for (int m = 0; m < 32; m++) { aq[m] = 0.f; at[m] = 0.f; }
    for (int kb = k0; kb < kend; kb += 32) {
        int kmax = min(32, kend - kb);
        for (int idx = tid; idx < 32 * 32; idx += 256) {
            int m = idx >> 5, kk = idx & 31;
            sA[m][kk] = (kk < kmax) ? g_bagz[(size_t)(m0 + m) * FEATP + kb + kk] : 0.f;
        }
        __syncthreads();
        const float* P1 = B1 + (size_t)kb * HH + col;
        const float* P2 = B2 + (size_t)kb * DD + col;
        int kk = 0;
        for (; kk + 2 <= kmax; kk += 2) {
            float q0 = P1[0], q1 = P1[HH];
            float t0 = P2[0], t1v = P2[DD];
            P1 += 2 * HH; P2 += 2 * DD;
#pragma unroll
            for (int m = 0; m < 32; m++) aq[m] += sA[m][kk] * q0;
#pragma unroll
            for (int m = 0; m < 32; m++) at[m] += sA[m][kk] * t0;
#pragma unroll
            for (int m = 0; m < 32; m++) aq[m] += sA[m][kk + 1] * q1;
#pragma unroll
            for (int m = 0; m < 32; m++) at[m] += sA[m][kk + 1] * t1v;
        }
        for (; kk < kmax; kk++) {
            float q0 = P1[0], t0 = P2[0]; P1 += HH; P2 += DD;
#pragma unroll
            for (int m = 0; m < 32; m++) { aq[m] += sA[m][kk] * q0; at[m] += sA[m][kk] * t0; }
        }
        __syncthreads();
    }
#pragma unroll
    for (int m = 0; m < 32; m++) {
        atomicAdd(&g_q[(size_t)(m0 + m) * HH + col], aq[m]);
        atomicAdd(&g_t1[(size_t)(m0 + m) * DD + col], at[m]);
    }
}

// ---------------- skinny GEMM (fcx part): t1 += fcx@Wc1[0:HH] --------------
__global__ __launch_bounds__(256) void skinny_fcx_kernel(const float* __restrict__ B) {
    __shared__ float sA[64][33];
    int tid = threadIdx.x;
    int col = blockIdx.x * 256 + tid;
    int nsplit = gridDim.y;
    int len = (HH + nsplit - 1) / nsplit;
    int k0 = blockIdx.y * len;
    int kend = min(HH, k0 + len);
    float acc[64];
#pragma unroll
    for (int m = 0; m < 64; m++) acc[m] = 0.f;
    for (int kb = k0; kb < kend; kb += 32) {
        int kmax = min(32, kend - kb);
        for (int idx = tid; idx < 64 * 32; idx += 256) {
            int m = idx >> 5, kk = idx & 31;
            sA[m][kk] = (kk < kmax) ? g_fcx[(size_t)m * HH + kb + kk] : 0.f;
        }
        __syncthreads();
        const float* Bp = B + (size_t)kb * DD + col;
        int kk = 0;
        for (; kk + 4 <= kmax; kk += 4) {
            float bv0 = Bp[0];
            float bv1 = Bp[DD];
            float bv2 = Bp[2 * DD];
            float bv3 = Bp[3 * DD];
            Bp += 4 * (size_t)DD;
#pragma unroll
            for (int m = 0; m < 64; m++) acc[m] += sA[m][kk] * bv0;
#pragma unroll
            for (int m = 0; m < 64; m++) acc[m] += sA[m][kk + 1] * bv1;
#pragma unroll
            for (int m = 0; m < 64; m++) acc[m] += sA[m][kk + 2] * bv2;
#pragma unroll
            for (int m = 0; m < 64; m++) acc[m] += sA[m][kk + 3] * bv3;
        }
        for (; kk < kmax; kk++) {
            float bv = Bp[0]; Bp += (size_t)DD;
#pragma unroll
            for (int m = 0; m < 64; m++) acc[m] += sA[m][kk] * bv;
        }
        __syncthreads();
    }
#pragma unroll
    for (int m = 0; m < 64; m++) atomicAdd(&g_t1[(size_t)m * DD + col], acc[m]);
}

// ---------------- cross attention (64 blocks, one per batch row) ----------
__global__ void cross_kernel() {
    int b = blockIdx.x, t = threadIdx.x;  // 256 threads
    __shared__ float red0[256], red1[256];
    const float* qp = g_q + b * HH;
    float d0 = 0.f, d1 = 0.f;
    for (int d = t; d < HH; d += 256) {
        float qv = qp[d];
        d0 += qv * g_k2[d];
        d1 += qv * g_k2[HH + d];
    }
    red0[t] = d0; red1[t] = d1;
    __syncthreads();
    for (int s = 128; s > 0; s >>= 1) {
        if (t < s) { red0[t] += red0[t + s]; red1[t] += red1[t + s]; }
        __syncthreads();
    }
    float x0 = red0[0] * (1.0f / 32.0f);
    float x1 = red1[0] * (1.0f / 32.0f);
    float m = fmaxf(x0, x1);
    float e0 = expf(x0 - m), e1 = expf(x1 - m);
    float inv = 1.f / (e0 + e1);
    float a0 = e0 * inv, a1 = e1 * inv;
    for (int d = t; d < HH; d += 256)
        g_fcx[b * HH + d] = a0 * g_v2[d] + a1 * g_v2[HH + d];
}

// ---------------- classifier head ----------------
__global__ void final_kernel(const float* __restrict__ Wc2, const float* __restrict__ bc2,
                             float* __restrict__ out, int out_size) {
    int b = blockIdx.x, t = threadIdx.x;
    float acc = 0.f;
    for (int d = t; d < DD; d += 256) acc += fmaxf(g_t1[b * DD + d], 0.f) * Wc2[d];
    __shared__ float red[256];
    red[t] = acc; __syncthreads();
    for (int s = 128; s > 0; s >>= 1) { if (t < s) red[t] += red[t + s]; __syncthreads(); }
    if (t == 0) {
        float y = 1.f / (1.f + expf(-(red[0] + bc2[0])));
        out[b] = y;
        if (64 + b < out_size) out[64 + b] = (y >= 0.5f) ? 1.f : 0.f;
    }
}

// ---------------- launch ----------------
extern "C" void kernel_launch(void* const* d_in, const int* in_sizes, int n_in,
                              void* d_out, int out_size) {
    const float* FC    = (const float*)d_in[0];
    const float* cc    = (const float*)d_in[1];
    const float* W1    = (const float*)d_in[2];
    const float* b1    = (const float*)d_in[3];
    const float* W2    = (const float*)d_in[4];
    const float* b2    = (const float*)d_in[5];
    const float* bn_g  = (const float*)d_in[6];
    const float* bn_b  = (const float*)d_in[7];
    const float* bn2_g = (const float*)d_in[8];
    const float* bn2_b = (const float*)d_in[9];
    const float* Wq    = (const float*)d_in[10];
    const float* bq    = (const float*)d_in[11];
    const float* Wk    = (const float*)d_in[12];
    const float* bk    = (const float*)d_in[13];
    const float* Wc1   = (const float*)d_in[14];
    const float* bc1   = (const float*)d_in[15];
    const float* Wc2   = (const float*)d_in[16];
    const float* bc2   = (const float*)d_in[17];
    float* out = (float*)d_out;

    cudaFuncSetAttribute(gemm_mma_kernel, cudaFuncAttributeMaxDynamicSharedMemorySize, GEMM_SMEM);

    init_off_kernel<<<ROI + INIT_BLOCKS, 256>>>(bq, bk, bc1);               // 1
    w1t_kernel<<<dim3(FEATP / 32, DD / 32), dim3(32, 8)>>>(W1, b2);         // 2
    gather_kernel<<<dim3(4, BW), 256>>>(FC);                                // 3
    gemm_mma_kernel<<<dim3(8, 64), 256, GEMM_SMEM>>>(b1, W2);               // 4 (ncu slot)
    pool_kernel<<<dim3(4, NB), 256>>>();
    bn_kernel<<<(FEAT + 255) / 256, 256>>>(cc, bn_g, bn_b, bn2_g, bn2_b);
    skinny_dual_kernel<<<dim3(4, 104, 3), 256>>>(Wq, Wc1 + (size_t)HH * DD, Wk);
    cross_kernel<<<NB, 256>>>();
    skinny_fcx_kernel<<<dim3(4, 16), 256>>>(Wc1);
    final_kernel<<<NB, 256>>>(Wc2, bc2, out, out_size);
}